// round 1
// baseline (speedup 1.0000x reference)
#include <cuda_runtime.h>
#include <math.h>

#define NN 50000
#define NE 800000
#define DD 128

// ---------------- scratch (device globals; no runtime alloc allowed) --------
__device__ float g_Ah[NN*DD];
__device__ float g_Bh[NN*DD];
__device__ float g_Dh[NN*DD];
__device__ float g_Eh[NN*DD];
__device__ float g_eij[NE*DD];            // 409.6 MB
__device__ float g_hnew[NN*DD];
__device__ int   g_deg[NN];
__device__ int   g_off[NN+1];
__device__ int   g_cur[NN];
__device__ int2  g_perm[NE];              // (edge_id, src[edge_id])
__device__ float g_sum_e[DD], g_sumsq_e[DD], g_sum_h[DD], g_sumsq_h[DD];

// ---------------- init: zero counters + stats --------------------------------
__global__ void k_init() {
    int i = blockIdx.x * 256 + threadIdx.x;
    if (i < NN) g_deg[i] = 0;
    if (i < DD) {
        g_sum_e[i] = 0.f; g_sumsq_e[i] = 0.f;
        g_sum_h[i] = 0.f; g_sumsq_h[i] = 0.f;
    }
}

// ---------------- node GEMMs: Ah,Bh,Dh,Eh = h@W + b --------------------------
// block = 256 threads, tile = 64 rows x 128 cols, micro = 4x8 per thread.
__global__ void __launch_bounds__(256) k_node_gemm(
    const float* __restrict__ h,
    const float* __restrict__ WA, const float* __restrict__ bA,
    const float* __restrict__ WB, const float* __restrict__ bB,
    const float* __restrict__ WD, const float* __restrict__ bD,
    const float* __restrict__ WE, const float* __restrict__ bE)
{
    extern __shared__ float sm[];
    float* sW = sm;            // 16384 floats (128x128 W)
    float* sH = sm + 16384;    // 8192 floats (64x128 h tile)
    const int t  = threadIdx.x;
    const int tx = t & 15;     // col group: cols tx*8 .. tx*8+7
    const int ty = t >> 4;     // row group: rows ty*4 .. ty*4+3
    const int rowBase = blockIdx.x * 64;

    {   // load h tile (coalesced float4)
        float4* sH4 = (float4*)sH;
        const float4* h4 = (const float4*)h;
        #pragma unroll
        for (int i = t; i < 2048; i += 256) {
            int gr = rowBase + (i >> 5);
            sH4[i] = (gr < NN) ? h4[gr*32 + (i & 31)] : make_float4(0.f,0.f,0.f,0.f);
        }
    }

    const float* Ws[4] = {WA, WB, WD, WE};
    const float* bs[4] = {bA, bB, bD, bE};
    float* outs[4] = {g_Ah, g_Bh, g_Dh, g_Eh};

    for (int m = 0; m < 4; m++) {
        __syncthreads();
        {
            float4* sW4 = (float4*)sW;
            const float4* W4 = (const float4*)Ws[m];
            #pragma unroll
            for (int i = t; i < 4096; i += 256) sW4[i] = W4[i];
        }
        __syncthreads();

        float acc[4][8];
        #pragma unroll
        for (int i = 0; i < 4; i++)
            #pragma unroll
            for (int j = 0; j < 8; j++) acc[i][j] = 0.f;

        #pragma unroll 4
        for (int k = 0; k < 128; k++) {
            const float4* wr = (const float4*)(sW + k*128 + tx*8);
            float4 w0 = wr[0], w1 = wr[1];
            #pragma unroll
            for (int i = 0; i < 4; i++) {
                float hv = sH[(ty*4+i)*128 + k];
                acc[i][0] = fmaf(hv, w0.x, acc[i][0]);
                acc[i][1] = fmaf(hv, w0.y, acc[i][1]);
                acc[i][2] = fmaf(hv, w0.z, acc[i][2]);
                acc[i][3] = fmaf(hv, w0.w, acc[i][3]);
                acc[i][4] = fmaf(hv, w1.x, acc[i][4]);
                acc[i][5] = fmaf(hv, w1.y, acc[i][5]);
                acc[i][6] = fmaf(hv, w1.z, acc[i][6]);
                acc[i][7] = fmaf(hv, w1.w, acc[i][7]);
            }
        }
        float4 b0 = *(const float4*)(bs[m] + tx*8);
        float4 b1 = *(const float4*)(bs[m] + tx*8 + 4);
        float* op = outs[m];
        #pragma unroll
        for (int i = 0; i < 4; i++) {
            int gr = rowBase + ty*4 + i;
            if (gr < NN) {
                float4* o4 = (float4*)(op + gr*128 + tx*8);
                o4[0] = make_float4(acc[i][0]+b0.x, acc[i][1]+b0.y, acc[i][2]+b0.z, acc[i][3]+b0.w);
                o4[1] = make_float4(acc[i][4]+b1.x, acc[i][5]+b1.y, acc[i][6]+b1.z, acc[i][7]+b1.w);
            }
        }
    }
}

// ---------------- edge GEMM + message + deg count + e-BN stats ---------------
// e_ij = e@WC + bC + Dh[src] + Eh[dst]; writes g_eij; accumulates column
// sum / sumsq for the e BatchNorm; counts in-degree of dst for CSR.
__global__ void __launch_bounds__(256) k_edge_gemm(
    const float* __restrict__ e,
    const float* __restrict__ WC, const float* __restrict__ bC,
    const int* __restrict__ src, const int* __restrict__ dst)
{
    extern __shared__ float sm[];
    float* sW   = sm;                 // 16384 floats
    float* sE   = sm + 16384;         // 8192 floats (reused as reduction buf)
    float* sBias= sm + 24576;         // 128 floats
    int*   sSrc = (int*)(sm + 24704); // 64 ints
    int*   sDst = sSrc + 64;          // 64 ints
    const int t  = threadIdx.x;
    const int tx = t & 15;
    const int ty = t >> 4;
    const int rowBase = blockIdx.x * 64;   // NE % 64 == 0, no row guard needed

    {
        float4* sE4 = (float4*)sE;
        const float4* e4 = (const float4*)e;
        #pragma unroll
        for (int i = t; i < 2048; i += 256) sE4[i] = e4[rowBase*32 + i];
        float4* sW4 = (float4*)sW;
        const float4* W4 = (const float4*)WC;
        #pragma unroll
        for (int i = t; i < 4096; i += 256) sW4[i] = W4[i];
        if (t < 128) sBias[t] = bC[t];
        if (t < 64) { sSrc[t] = src[rowBase + t]; sDst[t] = dst[rowBase + t]; }
    }
    __syncthreads();

    float acc[4][8];
    #pragma unroll
    for (int i = 0; i < 4; i++)
        #pragma unroll
        for (int j = 0; j < 8; j++) acc[i][j] = 0.f;

    #pragma unroll 4
    for (int k = 0; k < 128; k++) {
        const float4* wr = (const float4*)(sW + k*128 + tx*8);
        float4 w0 = wr[0], w1 = wr[1];
        #pragma unroll
        for (int i = 0; i < 4; i++) {
            float ev = sE[(ty*4+i)*128 + k];
            acc[i][0] = fmaf(ev, w0.x, acc[i][0]);
            acc[i][1] = fmaf(ev, w0.y, acc[i][1]);
            acc[i][2] = fmaf(ev, w0.z, acc[i][2]);
            acc[i][3] = fmaf(ev, w0.w, acc[i][3]);
            acc[i][4] = fmaf(ev, w1.x, acc[i][4]);
            acc[i][5] = fmaf(ev, w1.y, acc[i][5]);
            acc[i][6] = fmaf(ev, w1.z, acc[i][6]);
            acc[i][7] = fmaf(ev, w1.w, acc[i][7]);
        }
    }
    __syncthreads();   // sE no longer needed as input tile; reuse as reduction buf

    float colsum[8], colsq[8];
    #pragma unroll
    for (int j = 0; j < 8; j++) { colsum[j] = 0.f; colsq[j] = 0.f; }

    #pragma unroll
    for (int i = 0; i < 4; i++) {
        int row = ty*4 + i;
        int eg  = rowBase + row;
        int s   = sSrc[row];
        int dd  = sDst[row];
        const float4* Dh4 = (const float4*)(g_Dh + s*128  + tx*8);
        const float4* Eh4 = (const float4*)(g_Eh + dd*128 + tx*8);
        float4 d0 = Dh4[0], d1 = Dh4[1];
        float4 q0 = Eh4[0], q1 = Eh4[1];
        float v[8];
        v[0] = acc[i][0] + sBias[tx*8+0] + d0.x + q0.x;
        v[1] = acc[i][1] + sBias[tx*8+1] + d0.y + q0.y;
        v[2] = acc[i][2] + sBias[tx*8+2] + d0.z + q0.z;
        v[3] = acc[i][3] + sBias[tx*8+3] + d0.w + q0.w;
        v[4] = acc[i][4] + sBias[tx*8+4] + d1.x + q1.x;
        v[5] = acc[i][5] + sBias[tx*8+5] + d1.y + q1.y;
        v[6] = acc[i][6] + sBias[tx*8+6] + d1.z + q1.z;
        v[7] = acc[i][7] + sBias[tx*8+7] + d1.w + q1.w;
        float4* o4 = (float4*)(g_eij + (size_t)eg*128 + tx*8);
        o4[0] = make_float4(v[0], v[1], v[2], v[3]);
        o4[1] = make_float4(v[4], v[5], v[6], v[7]);
        #pragma unroll
        for (int j = 0; j < 8; j++) { colsum[j] += v[j]; colsq[j] += v[j]*v[j]; }
        if (tx == 0) atomicAdd(&g_deg[dd], 1);
    }

    // block reduction of column stats (16 ty-groups), then 256 global atomics
    float* sRsum = sE;           // 2048 floats
    float* sRsq  = sE + 2048;    // 2048 floats
    #pragma unroll
    for (int j = 0; j < 8; j++) {
        sRsum[ty*128 + tx*8 + j] = colsum[j];
        sRsq [ty*128 + tx*8 + j] = colsq[j];
    }
    __syncthreads();
    if (t < 128) {
        float a = 0.f, b = 0.f;
        #pragma unroll
        for (int r = 0; r < 16; r++) { a += sRsum[r*128 + t]; b += sRsq[r*128 + t]; }
        atomicAdd(&g_sum_e[t], a);
        atomicAdd(&g_sumsq_e[t], b);
    }
}

// ---------------- exclusive scan of degrees -> CSR offsets -------------------
__global__ void k_scan() {
    __shared__ int sbuf[1024];
    const int t = threadIdx.x;
    int carry = 0;
    for (int base = 0; base < NN; base += 1024) {
        int v = (base + t < NN) ? g_deg[base + t] : 0;
        sbuf[t] = v;
        __syncthreads();
        for (int d = 1; d < 1024; d <<= 1) {
            int x = (t >= d) ? sbuf[t - d] : 0;
            __syncthreads();
            sbuf[t] += x;
            __syncthreads();
        }
        int inc = sbuf[t];
        int tot = sbuf[1023];
        if (base + t < NN) {
            int ex = carry + inc - v;
            g_off[base + t] = ex;
            g_cur[base + t] = ex;
        }
        carry += tot;
        __syncthreads();
    }
    if (t == 0) g_off[NN] = carry;
}

// ---------------- scatter edges into CSR lists -------------------------------
__global__ void k_scatter(const int* __restrict__ src, const int* __restrict__ dst) {
    int i = blockIdx.x * 256 + threadIdx.x;
    if (i < NE) {
        int d = dst[i];
        int pos = atomicAdd(&g_cur[d], 1);
        g_perm[pos] = make_int2(i, src[i]);
    }
}

// ---------------- per-node gather: num/den reduction, h_new ------------------
__global__ void k_gather() {
    const int n = blockIdx.x;
    const int t = threadIdx.x;       // one feature column per thread
    const int s0 = g_off[n], s1 = g_off[n+1];
    float num = 0.f, den = 0.f;
    for (int j = s0; j < s1; j++) {
        int2 p = g_perm[j];
        float x  = g_eij[(size_t)p.x*128 + t];
        float sg = 1.f / (1.f + __expf(-x));
        num = fmaf(sg, g_Bh[p.y*128 + t], num);
        den += sg;
    }
    float hn = g_Ah[n*128 + t] + num / (den + 1e-6f);
    g_hnew[n*128 + t] = hn;
}

// ---------------- h BN stats --------------------------------------------------
__global__ void k_hstats() {
    const int t = threadIdx.x;       // column
    const int r0 = blockIdx.x * 250; // 200 blocks * 250 rows = 50000
    float a = 0.f, b = 0.f;
    for (int r = r0; r < r0 + 250; r++) {
        float v = g_hnew[r*128 + t];
        a += v; b += v*v;
    }
    atomicAdd(&g_sum_h[t], a);
    atomicAdd(&g_sumsq_h[t], b);
}

// ---------------- outputs: relu(BN(x)) ----------------------------------------
__global__ void k_hout(const float* __restrict__ gamma, const float* __restrict__ beta,
                       float* __restrict__ out) {
    __shared__ float sMean[DD], sScale[DD], sBeta[DD];
    const int t = threadIdx.x;
    if (t < DD) {
        float mean = g_sum_h[t] * (1.f / NN);
        float var  = g_sumsq_h[t] * (1.f / NN) - mean*mean;
        sMean[t] = mean;
        sScale[t] = gamma[t] * rsqrtf(var + 1e-5f);
        sBeta[t] = beta[t];
    }
    __syncthreads();
    int i4 = blockIdx.x * 256 + t;
    if (i4 < NN*32) {
        float4 x = ((const float4*)g_hnew)[i4];
        int c = (i4 & 31) * 4;
        float4 o;
        o.x = fmaxf(0.f, (x.x - sMean[c+0]) * sScale[c+0] + sBeta[c+0]);
        o.y = fmaxf(0.f, (x.y - sMean[c+1]) * sScale[c+1] + sBeta[c+1]);
        o.z = fmaxf(0.f, (x.z - sMean[c+2]) * sScale[c+2] + sBeta[c+2]);
        o.w = fmaxf(0.f, (x.w - sMean[c+3]) * sScale[c+3] + sBeta[c+3]);
        ((float4*)out)[i4] = o;
    }
}

__global__ void k_eout(const float* __restrict__ gamma, const float* __restrict__ beta,
                       float* __restrict__ out) {
    __shared__ float sMean[DD], sScale[DD], sBeta[DD];
    const int t = threadIdx.x;
    if (t < DD) {
        float mean = g_sum_e[t] * (1.f / NE);
        float var  = g_sumsq_e[t] * (1.f / NE) - mean*mean;
        sMean[t] = mean;
        sScale[t] = gamma[t] * rsqrtf(var + 1e-5f);
        sBeta[t] = beta[t];
    }
    __syncthreads();
    int i4 = blockIdx.x * 256 + t;
    if (i4 < NE*32) {
        float4 x = ((const float4*)g_eij)[i4];
        int c = (i4 & 31) * 4;
        float4 o;
        o.x = fmaxf(0.f, (x.x - sMean[c+0]) * sScale[c+0] + sBeta[c+0]);
        o.y = fmaxf(0.f, (x.y - sMean[c+1]) * sScale[c+1] + sBeta[c+1]);
        o.z = fmaxf(0.f, (x.z - sMean[c+2]) * sScale[c+2] + sBeta[c+2]);
        o.w = fmaxf(0.f, (x.w - sMean[c+3]) * sScale[c+3] + sBeta[c+3]);
        ((float4*)out)[i4] = o;
    }
}

// ---------------- launch ------------------------------------------------------
extern "C" void kernel_launch(void* const* d_in, const int* in_sizes, int n_in,
                              void* d_out, int out_size) {
    const float* h   = (const float*)d_in[0];
    const float* e   = (const float*)d_in[1];
    const int*   src = (const int*)  d_in[2];
    const int*   dst = (const int*)  d_in[3];
    const float* WA  = (const float*)d_in[4];  const float* bA = (const float*)d_in[5];
    const float* WB  = (const float*)d_in[6];  const float* bB = (const float*)d_in[7];
    const float* WC  = (const float*)d_in[8];  const float* bC = (const float*)d_in[9];
    const float* WD  = (const float*)d_in[10]; const float* bD = (const float*)d_in[11];
    const float* WE  = (const float*)d_in[12]; const float* bE = (const float*)d_in[13];
    const float* gamma_h = (const float*)d_in[14]; const float* beta_h = (const float*)d_in[15];
    const float* gamma_e = (const float*)d_in[16]; const float* beta_e = (const float*)d_in[17];
    float* out = (float*)d_out;

    const int SMEM_NODE = 24576 * 4;   // 96 KB
    const int SMEM_EDGE = 24832 * 4;   // 97 KB
    cudaFuncSetAttribute(k_node_gemm, cudaFuncAttributeMaxDynamicSharedMemorySize, SMEM_NODE);
    cudaFuncSetAttribute(k_edge_gemm, cudaFuncAttributeMaxDynamicSharedMemorySize, SMEM_EDGE);

    k_init<<<(NN + 255) / 256, 256>>>();
    k_node_gemm<<<(NN + 63) / 64, 256, SMEM_NODE>>>(h, WA, bA, WB, bB, WD, bD, WE, bE);
    k_edge_gemm<<<NE / 64, 256, SMEM_EDGE>>>(e, WC, bC, src, dst);
    k_scan<<<1, 1024>>>();
    k_scatter<<<(NE + 255) / 256, 256>>>(src, dst);
    k_gather<<<NN, 128>>>();
    k_hstats<<<200, 128>>>();
    k_hout<<<(NN * 32 + 255) / 256, 256>>>(gamma_h, beta_h, out);
    k_eout<<<(NE * 32 + 255) / 256, 256>>>(gamma_e, beta_e, out + (size_t)NN * DD);
}

// round 2
// speedup vs baseline: 1.0003x; 1.0003x over previous
#include <cuda_runtime.h>
#include <math.h>

#define NN 50000
#define NE 800000
#define DD 128

// ---------------- scratch (device globals; no runtime alloc allowed) --------
__device__ float g_Ah[NN*DD];
__device__ float g_Bh[NN*DD];
__device__ float g_Dh[NN*DD];
__device__ float g_Eh[NN*DD];
__device__ float g_eij[NE*DD];            // 409.6 MB
__device__ float g_hnew[NN*DD];
__device__ int   g_deg[NN];
__device__ int   g_off[NN+1];
__device__ int   g_cur[NN];
__device__ int2  g_perm[NE];              // (edge_id, src[edge_id])
__device__ float g_sum_e[DD], g_sumsq_e[DD], g_sum_h[DD], g_sumsq_h[DD];

// ---------------- init: zero counters + stats --------------------------------
__global__ void k_init() {
    int i = blockIdx.x * 256 + threadIdx.x;
    if (i < NN) g_deg[i] = 0;
    if (i < DD) {
        g_sum_e[i] = 0.f; g_sumsq_e[i] = 0.f;
        g_sum_h[i] = 0.f; g_sumsq_h[i] = 0.f;
    }
}

// ---------------- node GEMMs: Ah,Bh,Dh,Eh = h@W + b --------------------------
// block = 256 threads, tile = 64 rows x 128 cols, micro = 4x8 per thread.
__global__ void __launch_bounds__(256) k_node_gemm(
    const float* __restrict__ h,
    const float* __restrict__ WA, const float* __restrict__ bA,
    const float* __restrict__ WB, const float* __restrict__ bB,
    const float* __restrict__ WD, const float* __restrict__ bD,
    const float* __restrict__ WE, const float* __restrict__ bE)
{
    extern __shared__ float sm[];
    float* sW = sm;            // 16384 floats (128x128 W)
    float* sH = sm + 16384;    // 8192 floats (64x128 h tile)
    const int t  = threadIdx.x;
    const int tx = t & 15;     // col group: cols tx*8 .. tx*8+7
    const int ty = t >> 4;     // row group: rows ty*4 .. ty*4+3
    const int rowBase = blockIdx.x * 64;

    {   // load h tile (coalesced float4)
        float4* sH4 = (float4*)sH;
        const float4* h4 = (const float4*)h;
        #pragma unroll
        for (int i = t; i < 2048; i += 256) {
            int gr = rowBase + (i >> 5);
            sH4[i] = (gr < NN) ? h4[gr*32 + (i & 31)] : make_float4(0.f,0.f,0.f,0.f);
        }
    }

    const float* Ws[4] = {WA, WB, WD, WE};
    const float* bs[4] = {bA, bB, bD, bE};
    float* outs[4] = {g_Ah, g_Bh, g_Dh, g_Eh};

    for (int m = 0; m < 4; m++) {
        __syncthreads();
        {
            float4* sW4 = (float4*)sW;
            const float4* W4 = (const float4*)Ws[m];
            #pragma unroll
            for (int i = t; i < 4096; i += 256) sW4[i] = W4[i];
        }
        __syncthreads();

        float acc[4][8];
        #pragma unroll
        for (int i = 0; i < 4; i++)
            #pragma unroll
            for (int j = 0; j < 8; j++) acc[i][j] = 0.f;

        #pragma unroll 4
        for (int k = 0; k < 128; k++) {
            const float4* wr = (const float4*)(sW + k*128 + tx*8);
            float4 w0 = wr[0], w1 = wr[1];
            #pragma unroll
            for (int i = 0; i < 4; i++) {
                float hv = sH[(ty*4+i)*128 + k];
                acc[i][0] = fmaf(hv, w0.x, acc[i][0]);
                acc[i][1] = fmaf(hv, w0.y, acc[i][1]);
                acc[i][2] = fmaf(hv, w0.z, acc[i][2]);
                acc[i][3] = fmaf(hv, w0.w, acc[i][3]);
                acc[i][4] = fmaf(hv, w1.x, acc[i][4]);
                acc[i][5] = fmaf(hv, w1.y, acc[i][5]);
                acc[i][6] = fmaf(hv, w1.z, acc[i][6]);
                acc[i][7] = fmaf(hv, w1.w, acc[i][7]);
            }
        }
        float4 b0 = *(const float4*)(bs[m] + tx*8);
        float4 b1 = *(const float4*)(bs[m] + tx*8 + 4);
        float* op = outs[m];
        #pragma unroll
        for (int i = 0; i < 4; i++) {
            int gr = rowBase + ty*4 + i;
            if (gr < NN) {
                float4* o4 = (float4*)(op + gr*128 + tx*8);
                o4[0] = make_float4(acc[i][0]+b0.x, acc[i][1]+b0.y, acc[i][2]+b0.z, acc[i][3]+b0.w);
                o4[1] = make_float4(acc[i][4]+b1.x, acc[i][5]+b1.y, acc[i][6]+b1.z, acc[i][7]+b1.w);
            }
        }
    }
}

// ---------------- edge GEMM + message + deg count + e-BN stats ---------------
// e_ij = e@WC + bC + Dh[src] + Eh[dst]; writes g_eij; accumulates column
// sum / sumsq for the e BatchNorm; counts in-degree of dst for CSR.
__global__ void __launch_bounds__(256) k_edge_gemm(
    const float* __restrict__ e,
    const float* __restrict__ WC, const float* __restrict__ bC,
    const int* __restrict__ src, const int* __restrict__ dst)
{
    extern __shared__ float sm[];
    float* sW   = sm;                 // 16384 floats
    float* sE   = sm + 16384;         // 8192 floats (reused as reduction buf)
    float* sBias= sm + 24576;         // 128 floats
    int*   sSrc = (int*)(sm + 24704); // 64 ints
    int*   sDst = sSrc + 64;          // 64 ints
    const int t  = threadIdx.x;
    const int tx = t & 15;
    const int ty = t >> 4;
    const int rowBase = blockIdx.x * 64;   // NE % 64 == 0, no row guard needed

    {
        float4* sE4 = (float4*)sE;
        const float4* e4 = (const float4*)e;
        #pragma unroll
        for (int i = t; i < 2048; i += 256) sE4[i] = e4[rowBase*32 + i];
        float4* sW4 = (float4*)sW;
        const float4* W4 = (const float4*)WC;
        #pragma unroll
        for (int i = t; i < 4096; i += 256) sW4[i] = W4[i];
        if (t < 128) sBias[t] = bC[t];
        if (t < 64) { sSrc[t] = src[rowBase + t]; sDst[t] = dst[rowBase + t]; }
    }
    __syncthreads();

    float acc[4][8];
    #pragma unroll
    for (int i = 0; i < 4; i++)
        #pragma unroll
        for (int j = 0; j < 8; j++) acc[i][j] = 0.f;

    #pragma unroll 4
    for (int k = 0; k < 128; k++) {
        const float4* wr = (const float4*)(sW + k*128 + tx*8);
        float4 w0 = wr[0], w1 = wr[1];
        #pragma unroll
        for (int i = 0; i < 4; i++) {
            float ev = sE[(ty*4+i)*128 + k];
            acc[i][0] = fmaf(ev, w0.x, acc[i][0]);
            acc[i][1] = fmaf(ev, w0.y, acc[i][1]);
            acc[i][2] = fmaf(ev, w0.z, acc[i][2]);
            acc[i][3] = fmaf(ev, w0.w, acc[i][3]);
            acc[i][4] = fmaf(ev, w1.x, acc[i][4]);
            acc[i][5] = fmaf(ev, w1.y, acc[i][5]);
            acc[i][6] = fmaf(ev, w1.z, acc[i][6]);
            acc[i][7] = fmaf(ev, w1.w, acc[i][7]);
        }
    }
    __syncthreads();   // sE no longer needed as input tile; reuse as reduction buf

    float colsum[8], colsq[8];
    #pragma unroll
    for (int j = 0; j < 8; j++) { colsum[j] = 0.f; colsq[j] = 0.f; }

    #pragma unroll
    for (int i = 0; i < 4; i++) {
        int row = ty*4 + i;
        int eg  = rowBase + row;
        int s   = sSrc[row];
        int dd  = sDst[row];
        const float4* Dh4 = (const float4*)(g_Dh + s*128  + tx*8);
        const float4* Eh4 = (const float4*)(g_Eh + dd*128 + tx*8);
        float4 d0 = Dh4[0], d1 = Dh4[1];
        float4 q0 = Eh4[0], q1 = Eh4[1];
        float v[8];
        v[0] = acc[i][0] + sBias[tx*8+0] + d0.x + q0.x;
        v[1] = acc[i][1] + sBias[tx*8+1] + d0.y + q0.y;
        v[2] = acc[i][2] + sBias[tx*8+2] + d0.z + q0.z;
        v[3] = acc[i][3] + sBias[tx*8+3] + d0.w + q0.w;
        v[4] = acc[i][4] + sBias[tx*8+4] + d1.x + q1.x;
        v[5] = acc[i][5] + sBias[tx*8+5] + d1.y + q1.y;
        v[6] = acc[i][6] + sBias[tx*8+6] + d1.z + q1.z;
        v[7] = acc[i][7] + sBias[tx*8+7] + d1.w + q1.w;
        float4* o4 = (float4*)(g_eij + (size_t)eg*128 + tx*8);
        o4[0] = make_float4(v[0], v[1], v[2], v[3]);
        o4[1] = make_float4(v[4], v[5], v[6], v[7]);
        #pragma unroll
        for (int j = 0; j < 8; j++) { colsum[j] += v[j]; colsq[j] += v[j]*v[j]; }
        if (tx == 0) atomicAdd(&g_deg[dd], 1);
    }

    // block reduction of column stats (16 ty-groups), then 256 global atomics
    float* sRsum = sE;           // 2048 floats
    float* sRsq  = sE + 2048;    // 2048 floats
    #pragma unroll
    for (int j = 0; j < 8; j++) {
        sRsum[ty*128 + tx*8 + j] = colsum[j];
        sRsq [ty*128 + tx*8 + j] = colsq[j];
    }
    __syncthreads();
    if (t < 128) {
        float a = 0.f, b = 0.f;
        #pragma unroll
        for (int r = 0; r < 16; r++) { a += sRsum[r*128 + t]; b += sRsq[r*128 + t]; }
        atomicAdd(&g_sum_e[t], a);
        atomicAdd(&g_sumsq_e[t], b);
    }
}

// ---------------- exclusive scan of degrees -> CSR offsets -------------------
__global__ void k_scan() {
    __shared__ int sbuf[1024];
    const int t = threadIdx.x;
    int carry = 0;
    for (int base = 0; base < NN; base += 1024) {
        int v = (base + t < NN) ? g_deg[base + t] : 0;
        sbuf[t] = v;
        __syncthreads();
        for (int d = 1; d < 1024; d <<= 1) {
            int x = (t >= d) ? sbuf[t - d] : 0;
            __syncthreads();
            sbuf[t] += x;
            __syncthreads();
        }
        int inc = sbuf[t];
        int tot = sbuf[1023];
        if (base + t < NN) {
            int ex = carry + inc - v;
            g_off[base + t] = ex;
            g_cur[base + t] = ex;
        }
        carry += tot;
        __syncthreads();
    }
    if (t == 0) g_off[NN] = carry;
}

// ---------------- scatter edges into CSR lists -------------------------------
__global__ void k_scatter(const int* __restrict__ src, const int* __restrict__ dst) {
    int i = blockIdx.x * 256 + threadIdx.x;
    if (i < NE) {
        int d = dst[i];
        int pos = atomicAdd(&g_cur[d], 1);
        g_perm[pos] = make_int2(i, src[i]);
    }
}

// ---------------- per-node gather: num/den reduction, h_new ------------------
__global__ void k_gather() {
    const int n = blockIdx.x;
    const int t = threadIdx.x;       // one feature column per thread
    const int s0 = g_off[n], s1 = g_off[n+1];
    float num = 0.f, den = 0.f;
    for (int j = s0; j < s1; j++) {
        int2 p = g_perm[j];
        float x  = g_eij[(size_t)p.x*128 + t];
        float sg = 1.f / (1.f + __expf(-x));
        num = fmaf(sg, g_Bh[p.y*128 + t], num);
        den += sg;
    }
    float hn = g_Ah[n*128 + t] + num / (den + 1e-6f);
    g_hnew[n*128 + t] = hn;
}

// ---------------- h BN stats --------------------------------------------------
__global__ void k_hstats() {
    const int t = threadIdx.x;       // column
    const int r0 = blockIdx.x * 250; // 200 blocks * 250 rows = 50000
    float a = 0.f, b = 0.f;
    for (int r = r0; r < r0 + 250; r++) {
        float v = g_hnew[r*128 + t];
        a += v; b += v*v;
    }
    atomicAdd(&g_sum_h[t], a);
    atomicAdd(&g_sumsq_h[t], b);
}

// ---------------- outputs: relu(BN(x)) ----------------------------------------
__global__ void k_hout(const float* __restrict__ gamma, const float* __restrict__ beta,
                       float* __restrict__ out) {
    __shared__ float sMean[DD], sScale[DD], sBeta[DD];
    const int t = threadIdx.x;
    if (t < DD) {
        float mean = g_sum_h[t] * (1.f / NN);
        float var  = g_sumsq_h[t] * (1.f / NN) - mean*mean;
        sMean[t] = mean;
        sScale[t] = gamma[t] * rsqrtf(var + 1e-5f);
        sBeta[t] = beta[t];
    }
    __syncthreads();
    int i4 = blockIdx.x * 256 + t;
    if (i4 < NN*32) {
        float4 x = ((const float4*)g_hnew)[i4];
        int c = (i4 & 31) * 4;
        float4 o;
        o.x = fmaxf(0.f, (x.x - sMean[c+0]) * sScale[c+0] + sBeta[c+0]);
        o.y = fmaxf(0.f, (x.y - sMean[c+1]) * sScale[c+1] + sBeta[c+1]);
        o.z = fmaxf(0.f, (x.z - sMean[c+2]) * sScale[c+2] + sBeta[c+2]);
        o.w = fmaxf(0.f, (x.w - sMean[c+3]) * sScale[c+3] + sBeta[c+3]);
        ((float4*)out)[i4] = o;
    }
}

__global__ void k_eout(const float* __restrict__ gamma, const float* __restrict__ beta,
                       float* __restrict__ out) {
    __shared__ float sMean[DD], sScale[DD], sBeta[DD];
    const int t = threadIdx.x;
    if (t < DD) {
        float mean = g_sum_e[t] * (1.f / NE);
        float var  = g_sumsq_e[t] * (1.f / NE) - mean*mean;
        sMean[t] = mean;
        sScale[t] = gamma[t] * rsqrtf(var + 1e-5f);
        sBeta[t] = beta[t];
    }
    __syncthreads();
    int i4 = blockIdx.x * 256 + t;
    if (i4 < NE*32) {
        float4 x = ((const float4*)g_eij)[i4];
        int c = (i4 & 31) * 4;
        float4 o;
        o.x = fmaxf(0.f, (x.x - sMean[c+0]) * sScale[c+0] + sBeta[c+0]);
        o.y = fmaxf(0.f, (x.y - sMean[c+1]) * sScale[c+1] + sBeta[c+1]);
        o.z = fmaxf(0.f, (x.z - sMean[c+2]) * sScale[c+2] + sBeta[c+2]);
        o.w = fmaxf(0.f, (x.w - sMean[c+3]) * sScale[c+3] + sBeta[c+3]);
        ((float4*)out)[i4] = o;
    }
}

// ---------------- launch ------------------------------------------------------
extern "C" void kernel_launch(void* const* d_in, const int* in_sizes, int n_in,
                              void* d_out, int out_size) {
    const float* h   = (const float*)d_in[0];
    const float* e   = (const float*)d_in[1];
    const int*   src = (const int*)  d_in[2];
    const int*   dst = (const int*)  d_in[3];
    const float* WA  = (const float*)d_in[4];  const float* bA = (const float*)d_in[5];
    const float* WB  = (const float*)d_in[6];  const float* bB = (const float*)d_in[7];
    const float* WC  = (const float*)d_in[8];  const float* bC = (const float*)d_in[9];
    const float* WD  = (const float*)d_in[10]; const float* bD = (const float*)d_in[11];
    const float* WE  = (const float*)d_in[12]; const float* bE = (const float*)d_in[13];
    const float* gamma_h = (const float*)d_in[14]; const float* beta_h = (const float*)d_in[15];
    const float* gamma_e = (const float*)d_in[16]; const float* beta_e = (const float*)d_in[17];
    float* out = (float*)d_out;

    const int SMEM_NODE = 24576 * 4;   // 96 KB
    const int SMEM_EDGE = 24832 * 4;   // 97 KB
    cudaFuncSetAttribute(k_node_gemm, cudaFuncAttributeMaxDynamicSharedMemorySize, SMEM_NODE);
    cudaFuncSetAttribute(k_edge_gemm, cudaFuncAttributeMaxDynamicSharedMemorySize, SMEM_EDGE);

    k_init<<<(NN + 255) / 256, 256>>>();
    k_node_gemm<<<(NN + 63) / 64, 256, SMEM_NODE>>>(h, WA, bA, WB, bB, WD, bD, WE, bE);
    k_edge_gemm<<<NE / 64, 256, SMEM_EDGE>>>(e, WC, bC, src, dst);
    k_scan<<<1, 1024>>>();
    k_scatter<<<(NE + 255) / 256, 256>>>(src, dst);
    k_gather<<<NN, 128>>>();
    k_hstats<<<200, 128>>>();
    k_hout<<<(NN * 32 + 255) / 256, 256>>>(gamma_h, beta_h, out);
    k_eout<<<(NE * 32 + 255) / 256, 256>>>(gamma_e, beta_e, out + (size_t)NN * DD);
}

// round 4
// speedup vs baseline: 1.3383x; 1.3379x over previous
#include <cuda_runtime.h>
#include <cuda_bf16.h>
#include <stdint.h>
#include <math.h>

#define NN 50000
#define NE 800000
#define DD 128
#define NT_NODE 391
#define NT_EDGE 6250
#define EGRID 148

// ---------------- device scratch ---------------------------------------------
__device__ float g_Ah[NN*DD];
__device__ float g_Bh[NN*DD];
__device__ float g_Dh[NN*DD];
__device__ float g_Eh[NN*DD];
__device__ float g_eij[(size_t)NE*DD];
__device__ float g_hnew[NN*DD];
__device__ int   g_deg[NN];
__device__ int   g_off[NN+1];
__device__ int   g_cur[NN];
__device__ int2  g_perm[NE];
__device__ float g_sum_e[DD], g_sumsq_e[DD], g_sum_h[DD], g_sumsq_h[DD];
__device__ int   g_bsum[64], g_boff[64];
__device__ float g_slab[2][64][DD];
// W^T hi/lo: [mat][n*128 + k] bf16 (n-major so B is col-major for mma row.col)
__device__ __nv_bfloat16 g_WHi[5*16384];
__device__ __nv_bfloat16 g_WLo[5*16384];

// smem layout (bytes): bias | Whi | Wlo | Ahi | Alo  (rows padded to 136 bf16)
#define SM_BIAS 0
#define SM_WHI  512
#define SM_WLO  35328
#define SM_AHI  70144
#define SM_ALO  104960
#define SM_TOTAL 139776
#define RS 68   // row stride in 32-bit words (136 bf16)

// ---------------- mma.sync bf16 (baseline PTX, works on sm_103) ---------------
__device__ __forceinline__ void mma16816(float* c, const uint32_t* a, const uint32_t* b) {
    asm volatile("mma.sync.aligned.m16n8k16.row.col.f32.bf16.bf16.f32 "
        "{%0,%1,%2,%3}, {%4,%5,%6,%7}, {%8,%9}, {%0,%1,%2,%3};"
        : "+f"(c[0]), "+f"(c[1]), "+f"(c[2]), "+f"(c[3])
        : "r"(a[0]), "r"(a[1]), "r"(a[2]), "r"(a[3]), "r"(b[0]), "r"(b[1]));
}

// ---------------- small kernels -----------------------------------------------
__global__ void k_init() {
    int i = blockIdx.x * 256 + threadIdx.x;
    if (i < NN) g_deg[i] = 0;
    if (i < DD) { g_sum_e[i] = 0.f; g_sumsq_e[i] = 0.f; g_sum_h[i] = 0.f; g_sumsq_h[i] = 0.f; }
    if (i < 2*64*DD) ((float*)g_slab)[i] = 0.f;
}

__global__ void k_prep_w(const float* __restrict__ WA, const float* __restrict__ WB,
                         const float* __restrict__ WC, const float* __restrict__ WD,
                         const float* __restrict__ WE) {
    const float* Ws[5] = {WA, WB, WC, WD, WE};
    int mat = blockIdx.y;
    int i = blockIdx.x * 256 + threadIdx.x;   // 16384 per matrix
    int n = i >> 7, k = i & 127;
    float x = Ws[mat][k * 128 + n];           // transpose: B[n][k] = W[k][n]
    __nv_bfloat16 hb = __float2bfloat16(x);
    __nv_bfloat16 lb = __float2bfloat16(x - __bfloat162float(hb));
    g_WHi[mat * 16384 + i] = hb;
    g_WLo[mat * 16384 + i] = lb;
}

// ---------------- A tile: f32 -> bf16 hi/lo into padded smem ------------------
template<bool GUARD>
__device__ __forceinline__ void conv_tile(const float* __restrict__ src, int rowBase,
                                          char* sm_, int t) {
    __nv_bfloat16* sHi = (__nv_bfloat16*)(sm_ + SM_AHI);
    __nv_bfloat16* sLo = (__nv_bfloat16*)(sm_ + SM_ALO);
    #pragma unroll 4
    for (int i = t; i < 4096; i += 256) {     // 128 rows x 32 float4 groups
        int r = i >> 5, cg = (i & 31) << 2;
        float4 x;
        if (GUARD && (rowBase + r >= NN)) x = make_float4(0.f, 0.f, 0.f, 0.f);
        else x = *(const float4*)(src + (size_t)(rowBase + r) * DD + cg);
        __nv_bfloat162 h01 = __floats2bfloat162_rn(x.x, x.y);
        __nv_bfloat162 h23 = __floats2bfloat162_rn(x.z, x.w);
        float l0 = x.x - __bfloat162float(__low2bfloat16(h01));
        float l1 = x.y - __bfloat162float(__high2bfloat16(h01));
        float l2 = x.z - __bfloat162float(__low2bfloat16(h23));
        float l3 = x.w - __bfloat162float(__high2bfloat16(h23));
        __nv_bfloat162 q01 = __floats2bfloat162_rn(l0, l1);
        __nv_bfloat162 q23 = __floats2bfloat162_rn(l2, l3);
        int off = r * 136 + cg;
        *(uint2*)(sHi + off) = make_uint2(*(uint32_t*)&h01, *(uint32_t*)&h23);
        *(uint2*)(sLo + off) = make_uint2(*(uint32_t*)&q01, *(uint32_t*)&q23);
    }
}

// ---------------- load W (hi+lo) + bias into smem -----------------------------
__device__ __forceinline__ void load_w(char* sm_, int mat, const float* __restrict__ bias, int t) {
    const uint4* wh = (const uint4*)(g_WHi + mat * 16384);
    const uint4* wl = (const uint4*)(g_WLo + mat * 16384);
    __nv_bfloat16* dh = (__nv_bfloat16*)(sm_ + SM_WHI);
    __nv_bfloat16* dl = (__nv_bfloat16*)(sm_ + SM_WLO);
    #pragma unroll 2
    for (int i = t; i < 2048; i += 256) {     // 8-bf16 chunks
        int n = i >> 4, kg = i & 15;
        *(uint4*)(dh + n * 136 + kg * 8) = wh[i];
        *(uint4*)(dl + n * 136 + kg * 8) = wl[i];
    }
    if (t < 128) ((float*)(sm_ + SM_BIAS))[t] = bias[t];
}

// ---------------- one pass of warp-level GEMM (8 k-steps) ---------------------
__device__ __forceinline__ void warp_gemm(const uint32_t* __restrict__ sA,
                                          const uint32_t* __restrict__ sB,
                                          float acc[2][8][4], int rm, int cn, int lane) {
    int g = lane >> 2, t = lane & 3;
    #pragma unroll
    for (int s = 0; s < 8; s++) {
        uint32_t a[2][4];
        #pragma unroll
        for (int mt = 0; mt < 2; mt++) {
            int r0 = rm + mt * 16 + g;
            const uint32_t* p0 = sA + r0 * RS + s * 8 + t;
            const uint32_t* p1 = sA + (r0 + 8) * RS + s * 8 + t;
            a[mt][0] = p0[0]; a[mt][1] = p1[0]; a[mt][2] = p0[4]; a[mt][3] = p1[4];
        }
        uint32_t b[8][2];
        #pragma unroll
        for (int nt = 0; nt < 8; nt++) {
            const uint32_t* p = sB + (cn + nt * 8 + g) * RS + s * 8 + t;
            b[nt][0] = p[0]; b[nt][1] = p[4];
        }
        #pragma unroll
        for (int mt = 0; mt < 2; mt++)
            #pragma unroll
            for (int nt = 0; nt < 8; nt++)
                mma16816(acc[mt][nt], a[mt], b[nt]);
    }
}

__device__ __forceinline__ void compute_tile(char* sm_, float acc[2][8][4],
                                             int rm, int cn, int lane) {
    #pragma unroll
    for (int mt = 0; mt < 2; mt++)
        #pragma unroll
        for (int nt = 0; nt < 8; nt++)
            #pragma unroll
            for (int q = 0; q < 4; q++) acc[mt][nt][q] = 0.f;
    const uint32_t* aHi = (const uint32_t*)(sm_ + SM_AHI);
    const uint32_t* aLo = (const uint32_t*)(sm_ + SM_ALO);
    const uint32_t* wHi = (const uint32_t*)(sm_ + SM_WHI);
    const uint32_t* wLo = (const uint32_t*)(sm_ + SM_WLO);
    warp_gemm(aHi, wHi, acc, rm, cn, lane);
    warp_gemm(aHi, wLo, acc, rm, cn, lane);
    warp_gemm(aLo, wHi, acc, rm, cn, lane);
}

// ---------------- node GEMM: Ah,Bh,Dh,Eh --------------------------------------
__global__ void __launch_bounds__(256) k_node_hmma(
    const float* __restrict__ h,
    const float* __restrict__ bA, const float* __restrict__ bB,
    const float* __restrict__ bD, const float* __restrict__ bE)
{
    extern __shared__ char sm_[];
    const int t = threadIdx.x, lane = t & 31, w = t >> 5;
    const int rm = (w & 3) * 32, cn = (w >> 2) * 64;
    const int rowBase = blockIdx.x * 128;
    const float* sBias = (const float*)(sm_ + SM_BIAS);

    conv_tile<true>(h, rowBase, sm_, t);

    const float* const biases[4] = {bA, bB, bD, bE};
    float* const outs[4] = {g_Ah, g_Bh, g_Dh, g_Eh};
    const int img[4] = {0, 1, 3, 4};

    for (int mat = 0; mat < 4; mat++) {
        __syncthreads();
        load_w(sm_, img[mat], biases[mat], t);
        __syncthreads();
        float acc[2][8][4];
        compute_tile(sm_, acc, rm, cn, lane);
        // epilogue: + bias, store
        int g = lane >> 2, tq = lane & 3;
        float* out = outs[mat];
        #pragma unroll
        for (int mt = 0; mt < 2; mt++) {
            #pragma unroll
            for (int half = 0; half < 2; half++) {
                int row = rowBase + rm + mt * 16 + half * 8 + g;
                if (row < NN) {
                    #pragma unroll
                    for (int nt = 0; nt < 8; nt++) {
                        int col = cn + nt * 8 + tq * 2;
                        float2 v;
                        v.x = acc[mt][nt][half * 2 + 0] + sBias[col];
                        v.y = acc[mt][nt][half * 2 + 1] + sBias[col + 1];
                        *(float2*)(out + (size_t)row * DD + col) = v;
                    }
                }
            }
        }
    }
}

// ---------------- edge GEMM (persistent): e_ij = e@WC + bC + Dh[src] + Eh[dst]
__global__ void __launch_bounds__(256) k_edge_hmma(
    const float* __restrict__ e, const float* __restrict__ bC,
    const int* __restrict__ src, const int* __restrict__ dst)
{
    extern __shared__ char sm_[];
    const int t = threadIdx.x, lane = t & 31, w = t >> 5;
    const int rm = (w & 3) * 32, cn = (w >> 2) * 64;
    const float* sBias = (const float*)(sm_ + SM_BIAS);

    load_w(sm_, 2, bC, t);

    for (int tile = blockIdx.x; tile < NT_EDGE; tile += EGRID) {
        __syncthreads();                       // protect sA overwrite
        conv_tile<false>(e, tile * 128, sm_, t);
        __syncthreads();
        float acc[2][8][4];
        compute_tile(sm_, acc, rm, cn, lane);
        // fused epilogue
        int g = lane >> 2, tq = lane & 3;
        int rowBase = tile * 128;
        #pragma unroll
        for (int mt = 0; mt < 2; mt++) {
            #pragma unroll
            for (int half = 0; half < 2; half++) {
                int row = rowBase + rm + mt * 16 + half * 8 + g;
                int s = src[row], d = dst[row];
                if (cn == 0 && tq == 0) atomicAdd(&g_deg[d], 1);
                const float* Dp = g_Dh + (size_t)s * DD;
                const float* Ep = g_Eh + (size_t)d * DD;
                float* op = g_eij + (size_t)row * DD;
                #pragma unroll
                for (int nt = 0; nt < 8; nt++) {
                    int col = cn + nt * 8 + tq * 2;
                    float2 dv = *(const float2*)(Dp + col);
                    float2 ev = *(const float2*)(Ep + col);
                    float2 v;
                    v.x = acc[mt][nt][half * 2 + 0] + sBias[col]     + dv.x + ev.x;
                    v.y = acc[mt][nt][half * 2 + 1] + sBias[col + 1] + dv.y + ev.y;
                    *(float2*)(op + col) = v;
                }
            }
        }
    }
}

// ---------------- hierarchical scan -------------------------------------------
__global__ void k_scan1() {
    __shared__ int sbuf[1024];
    const int t = threadIdx.x;
    int gidx = blockIdx.x * 1024 + t;
    int v = (gidx < NN) ? g_deg[gidx] : 0;
    sbuf[t] = v;
    __syncthreads();
    for (int d = 1; d < 1024; d <<= 1) {
        int x = (t >= d) ? sbuf[t - d] : 0;
        __syncthreads();
        sbuf[t] += x;
        __syncthreads();
    }
    if (gidx < NN) g_off[gidx] = sbuf[t] - v;
    if (t == 1023) g_bsum[blockIdx.x] = sbuf[1023];
}
__global__ void k_scan2() {
    int a = 0;
    for (int b = 0; b < 49; b++) { g_boff[b] = a; a += g_bsum[b]; }
    g_off[NN] = a;
}
__global__ void k_scan3() {
    int gidx = blockIdx.x * 256 + threadIdx.x;
    if (gidx < NN) {
        int o = g_off[gidx] + g_boff[gidx >> 10];
        g_off[gidx] = o;
        g_cur[gidx] = o;
    }
}

__global__ void k_scatter(const int* __restrict__ src, const int* __restrict__ dst) {
    int i = blockIdx.x * 256 + threadIdx.x;
    if (i < NE) {
        int d = dst[i];
        int pos = atomicAdd(&g_cur[d], 1);
        g_perm[pos] = make_int2(i, src[i]);
    }
}

// ---------------- gather: h_new + fused e-BN stats ----------------------------
__global__ void k_gather() {
    const int n = blockIdx.x;
    const int t = threadIdx.x;
    const int s0 = g_off[n], s1 = g_off[n + 1];
    float num = 0.f, den = 0.f, es = 0.f, esq = 0.f;
    for (int j = s0; j < s1; j++) {
        int2 p = g_perm[j];
        float x = g_eij[(size_t)p.x * DD + t];
        float sg = 1.f / (1.f + __expf(-x));
        num = fmaf(sg, g_Bh[(size_t)p.y * DD + t], num);
        den += sg;
        es += x; esq = fmaf(x, x, esq);
    }
    float hn = g_Ah[(size_t)n * DD + t] + num / (den + 1e-6f);
    g_hnew[(size_t)n * DD + t] = hn;
    int sl = n & 63;
    atomicAdd(&g_slab[0][sl][t], es);
    atomicAdd(&g_slab[1][sl][t], esq);
}

__global__ void k_ered() {
    int t = threadIdx.x;
    float a = 0.f, b = 0.f;
    for (int j = 0; j < 64; j++) { a += g_slab[0][j][t]; b += g_slab[1][j][t]; }
    g_sum_e[t] = a; g_sumsq_e[t] = b;
}

__global__ void k_hstats() {
    const int t = threadIdx.x;
    const int r0 = blockIdx.x * 250;
    float a = 0.f, b = 0.f;
    for (int r = r0; r < r0 + 250; r++) {
        float v = g_hnew[(size_t)r * DD + t];
        a += v; b = fmaf(v, v, b);
    }
    atomicAdd(&g_sum_h[t], a);
    atomicAdd(&g_sumsq_h[t], b);
}

// ---------------- outputs: relu(BN(x)) ----------------------------------------
__global__ void k_hout(const float* __restrict__ gamma, const float* __restrict__ beta,
                       float* __restrict__ out) {
    __shared__ float sM[DD], sS[DD], sB[DD];
    const int t = threadIdx.x;
    if (t < DD) {
        float mean = g_sum_h[t] * (1.f / NN);
        float var  = g_sumsq_h[t] * (1.f / NN) - mean * mean;
        sM[t] = mean; sS[t] = gamma[t] * rsqrtf(var + 1e-5f); sB[t] = beta[t];
    }
    __syncthreads();
    int i4 = blockIdx.x * 256 + t;
    if (i4 < NN * 32) {
        float4 x = ((const float4*)g_hnew)[i4];
        int c = (i4 & 31) * 4;
        float4 o;
        o.x = fmaxf(0.f, (x.x - sM[c+0]) * sS[c+0] + sB[c+0]);
        o.y = fmaxf(0.f, (x.y - sM[c+1]) * sS[c+1] + sB[c+1]);
        o.z = fmaxf(0.f, (x.z - sM[c+2]) * sS[c+2] + sB[c+2]);
        o.w = fmaxf(0.f, (x.w - sM[c+3]) * sS[c+3] + sB[c+3]);
        ((float4*)out)[i4] = o;
    }
}

__global__ void k_eout(const float* __restrict__ gamma, const float* __restrict__ beta,
                       float* __restrict__ out) {
    __shared__ float sM[DD], sS[DD], sB[DD];
    const int t = threadIdx.x;
    if (t < DD) {
        float mean = g_sum_e[t] * (1.f / NE);
        float var  = g_sumsq_e[t] * (1.f / NE) - mean * mean;
        sM[t] = mean; sS[t] = gamma[t] * rsqrtf(var + 1e-5f); sB[t] = beta[t];
    }
    __syncthreads();
    size_t i4 = (size_t)blockIdx.x * 256 + t;
    if (i4 < (size_t)NE * 32) {
        float4 x = ((const float4*)g_eij)[i4];
        int c = (i4 & 31) * 4;
        float4 o;
        o.x = fmaxf(0.f, (x.x - sM[c+0]) * sS[c+0] + sB[c+0]);
        o.y = fmaxf(0.f, (x.y - sM[c+1]) * sS[c+1] + sB[c+1]);
        o.z = fmaxf(0.f, (x.z - sM[c+2]) * sS[c+2] + sB[c+2]);
        o.w = fmaxf(0.f, (x.w - sM[c+3]) * sS[c+3] + sB[c+3]);
        ((float4*)out)[i4] = o;
    }
}

// ---------------- launch ------------------------------------------------------
extern "C" void kernel_launch(void* const* d_in, const int* in_sizes, int n_in,
                              void* d_out, int out_size) {
    const float* h   = (const float*)d_in[0];
    const float* e   = (const float*)d_in[1];
    const int*   src = (const int*)  d_in[2];
    const int*   dst = (const int*)  d_in[3];
    const float* WA  = (const float*)d_in[4];  const float* bA = (const float*)d_in[5];
    const float* WB  = (const float*)d_in[6];  const float* bB = (const float*)d_in[7];
    const float* WC  = (const float*)d_in[8];  const float* bC = (const float*)d_in[9];
    const float* WD  = (const float*)d_in[10]; const float* bD = (const float*)d_in[11];
    const float* WE  = (const float*)d_in[12]; const float* bE = (const float*)d_in[13];
    const float* gamma_h = (const float*)d_in[14]; const float* beta_h = (const float*)d_in[15];
    const float* gamma_e = (const float*)d_in[16]; const float* beta_e = (const float*)d_in[17];
    float* out = (float*)d_out;

    cudaFuncSetAttribute(k_node_hmma, cudaFuncAttributeMaxDynamicSharedMemorySize, SM_TOTAL);
    cudaFuncSetAttribute(k_edge_hmma, cudaFuncAttributeMaxDynamicSharedMemorySize, SM_TOTAL);

    k_init<<<(NN + 255) / 256, 256>>>();
    k_prep_w<<<dim3(64, 5), 256>>>(WA, WB, WC, WD, WE);
    k_node_hmma<<<NT_NODE, 256, SM_TOTAL>>>(h, bA, bB, bD, bE);
    k_edge_hmma<<<EGRID, 256, SM_TOTAL>>>(e, bC, src, dst);
    k_scan1<<<49, 1024>>>();
    k_scan2<<<1, 1>>>();
    k_scan3<<<(NN + 255) / 256, 256>>>();
    k_scatter<<<(NE + 255) / 256, 256>>>(src, dst);
    k_gather<<<NN, 128>>>();
    k_ered<<<1, 128>>>();
    k_hstats<<<200, 128>>>();
    k_hout<<<(NN * 32 + 255) / 256, 256>>>(gamma_h, beta_h, out);
    k_eout<<<(int)(((size_t)NE * 32 + 255) / 256), 256>>>(gamma_e, beta_e, out + (size_t)NN * DD);
}

// round 5
// speedup vs baseline: 1.3412x; 1.0022x over previous
#include <cuda_runtime.h>
#include <cuda_bf16.h>
#include <stdint.h>
#include <math.h>

#define NN 50000
#define NE 800000
#define DD 128
#define NT_NODE 391
#define NT_EDGE 6250
#define EGRID 148

// ---------------- device scratch ---------------------------------------------
__device__ float g_Ah[NN*DD];
__device__ float g_Bh[NN*DD];
__device__ float g_Dh[NN*DD];
__device__ float g_Eh[NN*DD];
__device__ float g_eij[(size_t)NE*DD];
__device__ float g_hnew[NN*DD];
__device__ int   g_deg[NN];
__device__ int   g_off[NN+1];
__device__ int   g_cur[NN];
__device__ int2  g_perm[NE];
__device__ float g_sum_e[DD], g_sumsq_e[DD], g_sum_h[DD], g_sumsq_h[DD];
__device__ int   g_bsum[64], g_boff[64];
__device__ float g_slab[2][64][DD];
// W^T hi/lo: [mat][n*128 + k] bf16 (n-major so B is col-major for mma row.col)
__device__ __nv_bfloat16 g_WHi[5*16384];
__device__ __nv_bfloat16 g_WLo[5*16384];

// smem layout (bytes): bias | Whi | Wlo | A buffers (rows padded to 136 bf16)
#define SM_BIAS 0
#define SM_WHI  512
#define SM_WLO  35328
#define SM_A0   70144                 // buf0: hi | lo at +34816
#define SM_A1   139776                // buf1: hi | lo at +34816
#define SM_EDGE_TOTAL 209408
#define SM_NODE_TOTAL 139776
#define RS 68   // row stride in 32-bit words (136 bf16)

// ---------------- mma.sync bf16 (baseline PTX, works on sm_103) ---------------
__device__ __forceinline__ void mma16816(float* c, const uint32_t* a, const uint32_t* b) {
    asm volatile("mma.sync.aligned.m16n8k16.row.col.f32.bf16.bf16.f32 "
        "{%0,%1,%2,%3}, {%4,%5,%6,%7}, {%8,%9}, {%0,%1,%2,%3};"
        : "+f"(c[0]), "+f"(c[1]), "+f"(c[2]), "+f"(c[3])
        : "r"(a[0]), "r"(a[1]), "r"(a[2]), "r"(a[3]), "r"(b[0]), "r"(b[1]));
}

// ---------------- small kernels -----------------------------------------------
__global__ void k_init() {
    int i = blockIdx.x * 256 + threadIdx.x;
    if (i < NN) g_deg[i] = 0;
    if (i < DD) { g_sum_e[i] = 0.f; g_sumsq_e[i] = 0.f; g_sum_h[i] = 0.f; g_sumsq_h[i] = 0.f; }
    if (i < 2*64*DD) ((float*)g_slab)[i] = 0.f;
}

__global__ void k_prep_w(const float* __restrict__ WA, const float* __restrict__ WB,
                         const float* __restrict__ WC, const float* __restrict__ WD,
                         const float* __restrict__ WE) {
    const float* Ws[5] = {WA, WB, WC, WD, WE};
    int mat = blockIdx.y;
    int i = blockIdx.x * 256 + threadIdx.x;   // 16384 per matrix
    int n = i >> 7, k = i & 127;
    float x = Ws[mat][k * 128 + n];           // transpose: B[n][k] = W[k][n]
    __nv_bfloat16 hb = __float2bfloat16(x);
    __nv_bfloat16 lb = __float2bfloat16(x - __bfloat162float(hb));
    g_WHi[mat * 16384 + i] = hb;
    g_WLo[mat * 16384 + i] = lb;
}

// ---------------- helpers: convert float4 -> hi/lo bf16x2 pairs ---------------
__device__ __forceinline__ void split4(float4 x, uint2& hi, uint2& lo) {
    __nv_bfloat162 h01 = __floats2bfloat162_rn(x.x, x.y);
    __nv_bfloat162 h23 = __floats2bfloat162_rn(x.z, x.w);
    float l0 = x.x - __bfloat162float(__low2bfloat16(h01));
    float l1 = x.y - __bfloat162float(__high2bfloat16(h01));
    float l2 = x.z - __bfloat162float(__low2bfloat16(h23));
    float l3 = x.w - __bfloat162float(__high2bfloat16(h23));
    __nv_bfloat162 q01 = __floats2bfloat162_rn(l0, l1);
    __nv_bfloat162 q23 = __floats2bfloat162_rn(l2, l3);
    hi = make_uint2(*(uint32_t*)&h01, *(uint32_t*)&h23);
    lo = make_uint2(*(uint32_t*)&q01, *(uint32_t*)&q23);
}

// direct gmem -> smem conversion (512 threads, 8 float4 each)
template<bool GUARD>
__device__ __forceinline__ void conv_tile(const float* __restrict__ src, int rowBase,
                                          char* dstA, int t) {
    __nv_bfloat16* sHi = (__nv_bfloat16*)dstA;
    __nv_bfloat16* sLo = (__nv_bfloat16*)(dstA + 34816);
    #pragma unroll
    for (int i = 0; i < 8; i++) {
        int idx = t + i * 512;
        int r = idx >> 5, cg = (idx & 31) << 2;
        float4 x;
        if (GUARD && (rowBase + r >= NN)) x = make_float4(0.f, 0.f, 0.f, 0.f);
        else x = *(const float4*)(src + (size_t)(rowBase + r) * DD + cg);
        uint2 hi, lo;
        split4(x, hi, lo);
        int off = r * 136 + cg;
        *(uint2*)(sHi + off) = hi;
        *(uint2*)(sLo + off) = lo;
    }
}

// ---------------- load W (hi+lo) + bias into smem (512 threads) ---------------
__device__ __forceinline__ void load_w(char* sm_, int mat, const float* __restrict__ bias, int t) {
    const uint4* wh = (const uint4*)(g_WHi + mat * 16384);
    const uint4* wl = (const uint4*)(g_WLo + mat * 16384);
    __nv_bfloat16* dh = (__nv_bfloat16*)(sm_ + SM_WHI);
    __nv_bfloat16* dl = (__nv_bfloat16*)(sm_ + SM_WLO);
    #pragma unroll
    for (int i = t; i < 2048; i += 512) {     // 8-bf16 chunks
        int n = i >> 4, kg = i & 15;
        *(uint4*)(dh + n * 136 + kg * 8) = wh[i];
        *(uint4*)(dl + n * 136 + kg * 8) = wl[i];
    }
    if (t < 128) ((float*)(sm_ + SM_BIAS))[t] = bias[t];
}

// ---------------- one pass of warp-level GEMM (warp tile 32x32) ---------------
__device__ __forceinline__ void warp_pass(const uint32_t* __restrict__ sA,
                                          const uint32_t* __restrict__ sB,
                                          float acc[2][4][4], int rm, int cn, int lane) {
    int g = lane >> 2, tq = lane & 3;
    #pragma unroll
    for (int s = 0; s < 8; s++) {
        uint32_t a[2][4];
        #pragma unroll
        for (int mt = 0; mt < 2; mt++) {
            const uint32_t* p0 = sA + (rm + mt * 16 + g) * RS + s * 8 + tq;
            const uint32_t* p1 = p0 + 8 * RS;
            a[mt][0] = p0[0]; a[mt][1] = p1[0]; a[mt][2] = p0[4]; a[mt][3] = p1[4];
        }
        uint32_t b[4][2];
        #pragma unroll
        for (int nt = 0; nt < 4; nt++) {
            const uint32_t* p = sB + (cn + nt * 8 + g) * RS + s * 8 + tq;
            b[nt][0] = p[0]; b[nt][1] = p[4];
        }
        #pragma unroll
        for (int mt = 0; mt < 2; mt++)
            #pragma unroll
            for (int nt = 0; nt < 4; nt++)
                mma16816(acc[mt][nt], a[mt], b[nt]);
    }
}

__device__ __forceinline__ void compute_tile(char* sm_, char* aBuf, float acc[2][4][4],
                                             int rm, int cn, int lane) {
    #pragma unroll
    for (int mt = 0; mt < 2; mt++)
        #pragma unroll
        for (int nt = 0; nt < 4; nt++)
            #pragma unroll
            for (int q = 0; q < 4; q++) acc[mt][nt][q] = 0.f;
    const uint32_t* aHi = (const uint32_t*)aBuf;
    const uint32_t* aLo = (const uint32_t*)(aBuf + 34816);
    const uint32_t* wHi = (const uint32_t*)(sm_ + SM_WHI);
    const uint32_t* wLo = (const uint32_t*)(sm_ + SM_WLO);
    warp_pass(aHi, wHi, acc, rm, cn, lane);
    warp_pass(aHi, wLo, acc, rm, cn, lane);
    warp_pass(aLo, wHi, acc, rm, cn, lane);
}

// ---------------- node GEMM: Ah,Bh,Dh,Eh --------------------------------------
__global__ void __launch_bounds__(512, 1) k_node_hmma(
    const float* __restrict__ h,
    const float* __restrict__ bA, const float* __restrict__ bB,
    const float* __restrict__ bD, const float* __restrict__ bE)
{
    extern __shared__ char sm_[];
    const int t = threadIdx.x, lane = t & 31, w = t >> 5;
    const int rm = (w & 3) * 32, cn = (w >> 2) * 32;
    const int rowBase = blockIdx.x * 128;
    const float* sBias = (const float*)(sm_ + SM_BIAS);

    conv_tile<true>(h, rowBase, sm_ + SM_A0, t);

    const float* const biases[4] = {bA, bB, bD, bE};
    float* const outs[4] = {g_Ah, g_Bh, g_Dh, g_Eh};
    const int img[4] = {0, 1, 3, 4};

    for (int mat = 0; mat < 4; mat++) {
        __syncthreads();
        load_w(sm_, img[mat], biases[mat], t);
        __syncthreads();
        float acc[2][4][4];
        compute_tile(sm_, sm_ + SM_A0, acc, rm, cn, lane);
        int g = lane >> 2, tq = lane & 3;
        float* out = outs[mat];
        #pragma unroll
        for (int mt = 0; mt < 2; mt++) {
            #pragma unroll
            for (int half = 0; half < 2; half++) {
                int row = rowBase + rm + mt * 16 + half * 8 + g;
                if (row < NN) {
                    #pragma unroll
                    for (int nt = 0; nt < 4; nt++) {
                        int col = cn + nt * 8 + tq * 2;
                        float2 v;
                        v.x = acc[mt][nt][half * 2 + 0] + sBias[col];
                        v.y = acc[mt][nt][half * 2 + 1] + sBias[col + 1];
                        *(float2*)(out + (size_t)row * DD + col) = v;
                    }
                }
            }
        }
    }
}

// ---------------- edge GEMM (persistent, software-pipelined) ------------------
__global__ void __launch_bounds__(512, 1) k_edge_hmma(
    const float* __restrict__ e, const float* __restrict__ bC,
    const int* __restrict__ src, const int* __restrict__ dst)
{
    extern __shared__ char sm_[];
    const int t = threadIdx.x, lane = t & 31, w = t >> 5;
    const int rm = (w & 3) * 32, cn = (w >> 2) * 32;
    const float* sBias = (const float*)(sm_ + SM_BIAS);

    load_w(sm_, 2, bC, t);
    int tile = blockIdx.x;
    if (tile < NT_EDGE) conv_tile<false>(e, tile * 128, sm_ + SM_A0, t);
    __syncthreads();

    int par = 0;
    for (; tile < NT_EDGE; tile += EGRID) {
        int nextTile = tile + EGRID;
        bool hasNext = nextTile < NT_EDGE;
        // prefetch next A tile into registers (latency overlapped with MMAs)
        float4 pf[8];
        if (hasNext) {
            #pragma unroll
            for (int i = 0; i < 8; i++) {
                int idx = t + i * 512;
                pf[i] = *(const float4*)(e + (size_t)(nextTile * 128 + (idx >> 5)) * DD + ((idx & 31) << 2));
            }
        }
        // compute current
        float acc[2][4][4];
        compute_tile(sm_, sm_ + (par ? SM_A1 : SM_A0), acc, rm, cn, lane);
        // fused epilogue: bias + Dh[src] + Eh[dst], degree count
        {
            int g = lane >> 2, tq = lane & 3;
            int rowBase = tile * 128;
            #pragma unroll
            for (int mt = 0; mt < 2; mt++) {
                #pragma unroll
                for (int half = 0; half < 2; half++) {
                    int row = rowBase + rm + mt * 16 + half * 8 + g;
                    int s = src[row], d = dst[row];
                    if (cn == 0 && tq == 0) atomicAdd(&g_deg[d], 1);
                    const float* Dp = g_Dh + (size_t)s * DD;
                    const float* Ep = g_Eh + (size_t)d * DD;
                    float* op = g_eij + (size_t)row * DD;
                    #pragma unroll
                    for (int nt = 0; nt < 4; nt++) {
                        int col = cn + nt * 8 + tq * 2;
                        float2 dv = *(const float2*)(Dp + col);
                        float2 ev = *(const float2*)(Ep + col);
                        float2 v;
                        v.x = acc[mt][nt][half * 2 + 0] + sBias[col]     + dv.x + ev.x;
                        v.y = acc[mt][nt][half * 2 + 1] + sBias[col + 1] + dv.y + ev.y;
                        *(float2*)(op + col) = v;
                    }
                }
            }
        }
        // convert prefetched tile into the other buffer
        if (hasNext) {
            char* dstA = sm_ + (par ? SM_A0 : SM_A1);
            __nv_bfloat16* sHi = (__nv_bfloat16*)dstA;
            __nv_bfloat16* sLo = (__nv_bfloat16*)(dstA + 34816);
            #pragma unroll
            for (int i = 0; i < 8; i++) {
                int idx = t + i * 512;
                int r = idx >> 5, cg = (idx & 31) << 2;
                uint2 hi, lo;
                split4(pf[i], hi, lo);
                int off = r * 136 + cg;
                *(uint2*)(sHi + off) = hi;
                *(uint2*)(sLo + off) = lo;
            }
        }
        __syncthreads();
        par ^= 1;
    }
}

// ---------------- hierarchical scan -------------------------------------------
__global__ void k_scan1() {
    __shared__ int sbuf[1024];
    const int t = threadIdx.x;
    int gidx = blockIdx.x * 1024 + t;
    int v = (gidx < NN) ? g_deg[gidx] : 0;
    sbuf[t] = v;
    __syncthreads();
    for (int d = 1; d < 1024; d <<= 1) {
        int x = (t >= d) ? sbuf[t - d] : 0;
        __syncthreads();
        sbuf[t] += x;
        __syncthreads();
    }
    if (gidx < NN) g_off[gidx] = sbuf[t] - v;
    if (t == 1023) g_bsum[blockIdx.x] = sbuf[1023];
}
__global__ void k_scan2() {
    int a = 0;
    for (int b = 0; b < 49; b++) { g_boff[b] = a; a += g_bsum[b]; }
    g_off[NN] = a;
}
__global__ void k_scan3() {
    int gidx = blockIdx.x * 256 + threadIdx.x;
    if (gidx < NN) {
        int o = g_off[gidx] + g_boff[gidx >> 10];
        g_off[gidx] = o;
        g_cur[gidx] = o;
    }
}

__global__ void k_scatter(const int* __restrict__ src, const int* __restrict__ dst) {
    int i = blockIdx.x * 256 + threadIdx.x;
    if (i < NE) {
        int d = dst[i];
        int pos = atomicAdd(&g_cur[d], 1);
        g_perm[pos] = make_int2(i, src[i]);
    }
}

// ---------------- gather: h_new + fused e-BN stats ----------------------------
__global__ void k_gather() {
    const int n = blockIdx.x;
    const int t = threadIdx.x;
    const int s0 = g_off[n], s1 = g_off[n + 1];
    float num = 0.f, den = 0.f, es = 0.f, esq = 0.f;
    for (int j = s0; j < s1; j++) {
        int2 p = g_perm[j];
        float x = g_eij[(size_t)p.x * DD + t];
        float sg = 1.f / (1.f + __expf(-x));
        num = fmaf(sg, g_Bh[(size_t)p.y * DD + t], num);
        den += sg;
        es += x; esq = fmaf(x, x, esq);
    }
    float hn = g_Ah[(size_t)n * DD + t] + num / (den + 1e-6f);
    g_hnew[(size_t)n * DD + t] = hn;
    int sl = n & 63;
    atomicAdd(&g_slab[0][sl][t], es);
    atomicAdd(&g_slab[1][sl][t], esq);
}

__global__ void k_ered() {
    int t = threadIdx.x;
    float a = 0.f, b = 0.f;
    for (int j = 0; j < 64; j++) { a += g_slab[0][j][t]; b += g_slab[1][j][t]; }
    g_sum_e[t] = a; g_sumsq_e[t] = b;
}

__global__ void k_hstats() {
    const int t = threadIdx.x;
    const int r0 = blockIdx.x * 250;
    float a = 0.f, b = 0.f;
    for (int r = r0; r < r0 + 250; r++) {
        float v = g_hnew[(size_t)r * DD + t];
        a += v; b = fmaf(v, v, b);
    }
    atomicAdd(&g_sum_h[t], a);
    atomicAdd(&g_sumsq_h[t], b);
}

// ---------------- outputs: relu(BN(x)) ----------------------------------------
__global__ void k_hout(const float* __restrict__ gamma, const float* __restrict__ beta,
                       float* __restrict__ out) {
    __shared__ float sM[DD], sS[DD], sB[DD];
    const int t = threadIdx.x;
    if (t < DD) {
        float mean = g_sum_h[t] * (1.f / NN);
        float var  = g_sumsq_h[t] * (1.f / NN) - mean * mean;
        sM[t] = mean; sS[t] = gamma[t] * rsqrtf(var + 1e-5f); sB[t] = beta[t];
    }
    __syncthreads();
    int i4 = blockIdx.x * 256 + t;
    if (i4 < NN * 32) {
        float4 x = ((const float4*)g_hnew)[i4];
        int c = (i4 & 31) * 4;
        float4 o;
        o.x = fmaxf(0.f, (x.x - sM[c+0]) * sS[c+0] + sB[c+0]);
        o.y = fmaxf(0.f, (x.y - sM[c+1]) * sS[c+1] + sB[c+1]);
        o.z = fmaxf(0.f, (x.z - sM[c+2]) * sS[c+2] + sB[c+2]);
        o.w = fmaxf(0.f, (x.w - sM[c+3]) * sS[c+3] + sB[c+3]);
        ((float4*)out)[i4] = o;
    }
}

__global__ void k_eout(const float* __restrict__ gamma, const float* __restrict__ beta,
                       float* __restrict__ out) {
    __shared__ float sM[DD], sS[DD], sB[DD];
    const int t = threadIdx.x;
    if (t < DD) {
        float mean = g_sum_e[t] * (1.f / NE);
        float var  = g_sumsq_e[t] * (1.f / NE) - mean * mean;
        sM[t] = mean; sS[t] = gamma[t] * rsqrtf(var + 1e-5f); sB[t] = beta[t];
    }
    __syncthreads();
    size_t i4 = (size_t)blockIdx.x * 256 + t;
    if (i4 < (size_t)NE * 32) {
        float4 x = ((const float4*)g_eij)[i4];
        int c = (i4 & 31) * 4;
        float4 o;
        o.x = fmaxf(0.f, (x.x - sM[c+0]) * sS[c+0] + sB[c+0]);
        o.y = fmaxf(0.f, (x.y - sM[c+1]) * sS[c+1] + sB[c+1]);
        o.z = fmaxf(0.f, (x.z - sM[c+2]) * sS[c+2] + sB[c+2]);
        o.w = fmaxf(0.f, (x.w - sM[c+3]) * sS[c+3] + sB[c+3]);
        ((float4*)out)[i4] = o;
    }
}

// ---------------- launch ------------------------------------------------------
extern "C" void kernel_launch(void* const* d_in, const int* in_sizes, int n_in,
                              void* d_out, int out_size) {
    const float* h   = (const float*)d_in[0];
    const float* e   = (const float*)d_in[1];
    const int*   src = (const int*)  d_in[2];
    const int*   dst = (const int*)  d_in[3];
    const float* WA  = (const float*)d_in[4];  const float* bA = (const float*)d_in[5];
    const float* WB  = (const float*)d_in[6];  const float* bB = (const float*)d_in[7];
    const float* WC  = (const float*)d_in[8];  const float* bC = (const float*)d_in[9];
    const float* WD  = (const float*)d_in[10]; const float* bD = (const float*)d_in[11];
    const float* WE  = (const float*)d_in[12]; const float* bE = (const float*)d_in[13];
    const float* gamma_h = (const float*)d_in[14]; const float* beta_h = (const float*)d_in[15];
    const float* gamma_e = (const float*)d_in[16]; const float* beta_e = (const float*)d_in[17];
    float* out = (float*)d_out;

    cudaFuncSetAttribute(k_node_hmma, cudaFuncAttributeMaxDynamicSharedMemorySize, SM_NODE_TOTAL);
    cudaFuncSetAttribute(k_edge_hmma, cudaFuncAttributeMaxDynamicSharedMemorySize, SM_EDGE_TOTAL);

    k_init<<<(NN + 255) / 256, 256>>>();
    k_prep_w<<<dim3(64, 5), 256>>>(WA, WB, WC, WD, WE);
    k_node_hmma<<<NT_NODE, 512, SM_NODE_TOTAL>>>(h, bA, bB, bD, bE);
    k_edge_hmma<<<EGRID, 512, SM_EDGE_TOTAL>>>(e, bC, src, dst);
    k_scan1<<<49, 1024>>>();
    k_scan2<<<1, 1>>>();
    k_scan3<<<(NN + 255) / 256, 256>>>();
    k_scatter<<<(NE + 255) / 256, 256>>>(src, dst);
    k_gather<<<NN, 128>>>();
    k_ered<<<1, 128>>>();
    k_hstats<<<200, 128>>>();
    k_hout<<<(NN * 32 + 255) / 256, 256>>>(gamma_h, beta_h, out);
    k_eout<<<(int)(((size_t)NE * 32 + 255) / 256), 256>>>(gamma_e, beta_e, out + (size_t)NN * DD);
}

// round 6
// speedup vs baseline: 1.3455x; 1.0032x over previous
#include <cuda_runtime.h>
#include <cuda_bf16.h>
#include <stdint.h>
#include <math.h>

#define NN 50000
#define NE 800000
#define DD 128
#define NT_NODE 391
#define NT_EDGE 6250
#define EGRID 148

// ---------------- device scratch ---------------------------------------------
__device__ float g_Ah[NN*DD];
__device__ float g_Bh[NN*DD];
__device__ float g_Dh[NN*DD];
__device__ float g_Eh[NN*DD];
__device__ float g_eij[(size_t)NE*DD];
__device__ float g_hnew[NN*DD];
__device__ int   g_deg[NN];
__device__ int   g_off[NN+1];
__device__ int   g_cur[NN];
__device__ int2  g_perm[NE];
__device__ float g_sum_e[DD], g_sumsq_e[DD], g_sum_h[DD], g_sumsq_h[DD];
__device__ int   g_bsum[64], g_boff[64];
__device__ float g_slab[2][64][DD];
// W^T hi/lo: [mat][n*128 + k] bf16 (n-major so B is col-major for mma row.col)
__device__ __nv_bfloat16 g_WHi[5*16384];
__device__ __nv_bfloat16 g_WLo[5*16384];

// smem layout (bytes): bias | Whi | Wlo | A buffers (rows padded to 136 bf16)
#define SM_BIAS 0
#define SM_WHI  512
#define SM_WLO  35328
#define SM_A0   70144                 // buf0: hi | lo at +34816
#define SM_A1   139776                // buf1: hi | lo at +34816
#define SM_EDGE_TOTAL 209408
#define SM_NODE_TOTAL 139776
#define RS 68   // row stride in 32-bit words (136 bf16)

// ---------------- mma.sync bf16 (baseline PTX, works on sm_103) ---------------
__device__ __forceinline__ void mma16816(float* c, const uint32_t* a, const uint32_t* b) {
    asm volatile("mma.sync.aligned.m16n8k16.row.col.f32.bf16.bf16.f32 "
        "{%0,%1,%2,%3}, {%4,%5,%6,%7}, {%8,%9}, {%0,%1,%2,%3};"
        : "+f"(c[0]), "+f"(c[1]), "+f"(c[2]), "+f"(c[3])
        : "r"(a[0]), "r"(a[1]), "r"(a[2]), "r"(a[3]), "r"(b[0]), "r"(b[1]));
}

// ---------------- small kernels -----------------------------------------------
__global__ void k_init() {
    int i = blockIdx.x * 256 + threadIdx.x;
    if (i < NN) g_deg[i] = 0;
    if (i < DD) { g_sum_e[i] = 0.f; g_sumsq_e[i] = 0.f; g_sum_h[i] = 0.f; g_sumsq_h[i] = 0.f; }
    if (i < 2*64*DD) ((float*)g_slab)[i] = 0.f;
}

__global__ void k_prep_w(const float* __restrict__ WA, const float* __restrict__ WB,
                         const float* __restrict__ WC, const float* __restrict__ WD,
                         const float* __restrict__ WE) {
    const float* Ws[5] = {WA, WB, WC, WD, WE};
    int mat = blockIdx.y;
    int i = blockIdx.x * 256 + threadIdx.x;   // 16384 per matrix
    int n = i >> 7, k = i & 127;
    float x = Ws[mat][k * 128 + n];           // transpose: B[n][k] = W[k][n]
    __nv_bfloat16 hb = __float2bfloat16(x);
    __nv_bfloat16 lb = __float2bfloat16(x - __bfloat162float(hb));
    g_WHi[mat * 16384 + i] = hb;
    g_WLo[mat * 16384 + i] = lb;
}

// ---------------- helpers: convert float4 -> hi/lo bf16x2 pairs ---------------
__device__ __forceinline__ void split4(float4 x, uint2& hi, uint2& lo) {
    __nv_bfloat162 h01 = __floats2bfloat162_rn(x.x, x.y);
    __nv_bfloat162 h23 = __floats2bfloat162_rn(x.z, x.w);
    float l0 = x.x - __bfloat162float(__low2bfloat16(h01));
    float l1 = x.y - __bfloat162float(__high2bfloat16(h01));
    float l2 = x.z - __bfloat162float(__low2bfloat16(h23));
    float l3 = x.w - __bfloat162float(__high2bfloat16(h23));
    __nv_bfloat162 q01 = __floats2bfloat162_rn(l0, l1);
    __nv_bfloat162 q23 = __floats2bfloat162_rn(l2, l3);
    hi = make_uint2(*(uint32_t*)&h01, *(uint32_t*)&h23);
    lo = make_uint2(*(uint32_t*)&q01, *(uint32_t*)&q23);
}

// direct gmem -> smem conversion (512 threads, 8 float4 each)
template<bool GUARD>
__device__ __forceinline__ void conv_tile(const float* __restrict__ src, int rowBase,
                                          char* dstA, int t) {
    __nv_bfloat16* sHi = (__nv_bfloat16*)dstA;
    __nv_bfloat16* sLo = (__nv_bfloat16*)(dstA + 34816);
    #pragma unroll
    for (int i = 0; i < 8; i++) {
        int idx = t + i * 512;
        int r = idx >> 5, cg = (idx & 31) << 2;
        float4 x;
        if (GUARD && (rowBase + r >= NN)) x = make_float4(0.f, 0.f, 0.f, 0.f);
        else x = *(const float4*)(src + (size_t)(rowBase + r) * DD + cg);
        uint2 hi, lo;
        split4(x, hi, lo);
        int off = r * 136 + cg;
        *(uint2*)(sHi + off) = hi;
        *(uint2*)(sLo + off) = lo;
    }
}

// ---------------- load W (hi+lo) + bias into smem (512 threads) ---------------
__device__ __forceinline__ void load_w(char* sm_, int mat, const float* __restrict__ bias, int t) {
    const uint4* wh = (const uint4*)(g_WHi + mat * 16384);
    const uint4* wl = (const uint4*)(g_WLo + mat * 16384);
    __nv_bfloat16* dh = (__nv_bfloat16*)(sm_ + SM_WHI);
    __nv_bfloat16* dl = (__nv_bfloat16*)(sm_ + SM_WLO);
    #pragma unroll
    for (int i = t; i < 2048; i += 512) {     // 8-bf16 chunks
        int n = i >> 4, kg = i & 15;
        *(uint4*)(dh + n * 136 + kg * 8) = wh[i];
        *(uint4*)(dl + n * 136 + kg * 8) = wl[i];
    }
    if (t < 128) ((float*)(sm_ + SM_BIAS))[t] = bias[t];
}

// ---------------- one pass of warp-level GEMM (warp tile 32x32) ---------------
__device__ __forceinline__ void warp_pass(const uint32_t* __restrict__ sA,
                                          const uint32_t* __restrict__ sB,
                                          float acc[2][4][4], int rm, int cn, int lane) {
    int g = lane >> 2, tq = lane & 3;
    #pragma unroll
    for (int s = 0; s < 8; s++) {
        uint32_t a[2][4];
        #pragma unroll
        for (int mt = 0; mt < 2; mt++) {
            const uint32_t* p0 = sA + (rm + mt * 16 + g) * RS + s * 8 + tq;
            const uint32_t* p1 = p0 + 8 * RS;
            a[mt][0] = p0[0]; a[mt][1] = p1[0]; a[mt][2] = p0[4]; a[mt][3] = p1[4];
        }
        uint32_t b[4][2];
        #pragma unroll
        for (int nt = 0; nt < 4; nt++) {
            const uint32_t* p = sB + (cn + nt * 8 + g) * RS + s * 8 + tq;
            b[nt][0] = p[0]; b[nt][1] = p[4];
        }
        #pragma unroll
        for (int mt = 0; mt < 2; mt++)
            #pragma unroll
            for (int nt = 0; nt < 4; nt++)
                mma16816(acc[mt][nt], a[mt], b[nt]);
    }
}

__device__ __forceinline__ void compute_tile(char* sm_, char* aBuf, float acc[2][4][4],
                                             int rm, int cn, int lane) {
    #pragma unroll
    for (int mt = 0; mt < 2; mt++)
        #pragma unroll
        for (int nt = 0; nt < 4; nt++)
            #pragma unroll
            for (int q = 0; q < 4; q++) acc[mt][nt][q] = 0.f;
    const uint32_t* aHi = (const uint32_t*)aBuf;
    const uint32_t* aLo = (const uint32_t*)(aBuf + 34816);
    const uint32_t* wHi = (const uint32_t*)(sm_ + SM_WHI);
    const uint32_t* wLo = (const uint32_t*)(sm_ + SM_WLO);
    warp_pass(aHi, wHi, acc, rm, cn, lane);
    warp_pass(aHi, wLo, acc, rm, cn, lane);
    warp_pass(aLo, wHi, acc, rm, cn, lane);
}

// ---------------- node GEMM: Ah,Bh,Dh,Eh --------------------------------------
__global__ void __launch_bounds__(512, 1) k_node_hmma(
    const float* __restrict__ h,
    const float* __restrict__ bA, const float* __restrict__ bB,
    const float* __restrict__ bD, const float* __restrict__ bE)
{
    extern __shared__ char sm_[];
    const int t = threadIdx.x, lane = t & 31, w = t >> 5;
    const int rm = (w & 3) * 32, cn = (w >> 2) * 32;
    const int rowBase = blockIdx.x * 128;
    const float* sBias = (const float*)(sm_ + SM_BIAS);

    conv_tile<true>(h, rowBase, sm_ + SM_A0, t);

    const float* const biases[4] = {bA, bB, bD, bE};
    float* const outs[4] = {g_Ah, g_Bh, g_Dh, g_Eh};
    const int img[4] = {0, 1, 3, 4};

    for (int mat = 0; mat < 4; mat++) {
        __syncthreads();
        load_w(sm_, img[mat], biases[mat], t);
        __syncthreads();
        float acc[2][4][4];
        compute_tile(sm_, sm_ + SM_A0, acc, rm, cn, lane);
        int g = lane >> 2, tq = lane & 3;
        float* out = outs[mat];
        #pragma unroll
        for (int mt = 0; mt < 2; mt++) {
            #pragma unroll
            for (int half = 0; half < 2; half++) {
                int row = rowBase + rm + mt * 16 + half * 8 + g;
                if (row < NN) {
                    #pragma unroll
                    for (int nt = 0; nt < 4; nt++) {
                        int col = cn + nt * 8 + tq * 2;
                        float2 v;
                        v.x = acc[mt][nt][half * 2 + 0] + sBias[col];
                        v.y = acc[mt][nt][half * 2 + 1] + sBias[col + 1];
                        *(float2*)(out + (size_t)row * DD + col) = v;
                    }
                }
            }
        }
    }
}

// ---------------- edge GEMM (persistent, software-pipelined) ------------------
__global__ void __launch_bounds__(512, 1) k_edge_hmma(
    const float* __restrict__ e, const float* __restrict__ bC,
    const int* __restrict__ src, const int* __restrict__ dst)
{
    extern __shared__ char sm_[];
    const int t = threadIdx.x, lane = t & 31, w = t >> 5;
    const int rm = (w & 3) * 32, cn = (w >> 2) * 32;
    const float* sBias = (const float*)(sm_ + SM_BIAS);

    load_w(sm_, 2, bC, t);
    int tile = blockIdx.x;
    if (tile < NT_EDGE) conv_tile<false>(e, tile * 128, sm_ + SM_A0, t);
    __syncthreads();

    int par = 0;
    for (; tile < NT_EDGE; tile += EGRID) {
        int nextTile = tile + EGRID;
        bool hasNext = nextTile < NT_EDGE;
        // prefetch next A tile into registers (latency overlapped with MMAs)
        float4 pf[8];
        if (hasNext) {
            #pragma unroll
            for (int i = 0; i < 8; i++) {
                int idx = t + i * 512;
                pf[i] = *(const float4*)(e + (size_t)(nextTile * 128 + (idx >> 5)) * DD + ((idx & 31) << 2));
            }
        }
        // compute current
        float acc[2][4][4];
        compute_tile(sm_, sm_ + (par ? SM_A1 : SM_A0), acc, rm, cn, lane);
        // fused epilogue: bias + Dh[src] + Eh[dst], degree count
        {
            int g = lane >> 2, tq = lane & 3;
            int rowBase = tile * 128;
            #pragma unroll
            for (int mt = 0; mt < 2; mt++) {
                #pragma unroll
                for (int half = 0; half < 2; half++) {
                    int row = rowBase + rm + mt * 16 + half * 8 + g;
                    int s = src[row], d = dst[row];
                    if (cn == 0 && tq == 0) atomicAdd(&g_deg[d], 1);
                    const float* Dp = g_Dh + (size_t)s * DD;
                    const float* Ep = g_Eh + (size_t)d * DD;
                    float* op = g_eij + (size_t)row * DD;
                    #pragma unroll
                    for (int nt = 0; nt < 4; nt++) {
                        int col = cn + nt * 8 + tq * 2;
                        float2 dv = *(const float2*)(Dp + col);
                        float2 ev = *(const float2*)(Ep + col);
                        float2 v;
                        v.x = acc[mt][nt][half * 2 + 0] + sBias[col]     + dv.x + ev.x;
                        v.y = acc[mt][nt][half * 2 + 1] + sBias[col + 1] + dv.y + ev.y;
                        *(float2*)(op + col) = v;
                    }
                }
            }
        }
        // convert prefetched tile into the other buffer
        if (hasNext) {
            char* dstA = sm_ + (par ? SM_A0 : SM_A1);
            __nv_bfloat16* sHi = (__nv_bfloat16*)dstA;
            __nv_bfloat16* sLo = (__nv_bfloat16*)(dstA + 34816);
            #pragma unroll
            for (int i = 0; i < 8; i++) {
                int idx = t + i * 512;
                int r = idx >> 5, cg = (idx & 31) << 2;
                uint2 hi, lo;
                split4(pf[i], hi, lo);
                int off = r * 136 + cg;
                *(uint2*)(sHi + off) = hi;
                *(uint2*)(sLo + off) = lo;
            }
        }
        __syncthreads();
        par ^= 1;
    }
}

// ---------------- hierarchical scan -------------------------------------------
__global__ void k_scan1() {
    __shared__ int sbuf[1024];
    const int t = threadIdx.x;
    int gidx = blockIdx.x * 1024 + t;
    int v = (gidx < NN) ? g_deg[gidx] : 0;
    sbuf[t] = v;
    __syncthreads();
    for (int d = 1; d < 1024; d <<= 1) {
        int x = (t >= d) ? sbuf[t - d] : 0;
        __syncthreads();
        sbuf[t] += x;
        __syncthreads();
    }
    if (gidx < NN) g_off[gidx] = sbuf[t] - v;
    if (t == 1023) g_bsum[blockIdx.x] = sbuf[1023];
}
__global__ void k_scan2() {
    int a = 0;
    for (int b = 0; b < 49; b++) { g_boff[b] = a; a += g_bsum[b]; }
    g_off[NN] = a;
}
__global__ void k_scan3() {
    int gidx = blockIdx.x * 256 + threadIdx.x;
    if (gidx < NN) {
        int o = g_off[gidx] + g_boff[gidx >> 10];
        g_off[gidx] = o;
        g_cur[gidx] = o;
    }
}

__global__ void k_scatter(const int* __restrict__ src, const int* __restrict__ dst) {
    int i = blockIdx.x * 256 + threadIdx.x;
    if (i < NE) {
        int d = dst[i];
        int pos = atomicAdd(&g_cur[d], 1);
        g_perm[pos] = make_int2(i, src[i]);
    }
}

// ---------------- gather: h_new + fused e-BN stats ----------------------------
__global__ void k_gather() {
    const int n = blockIdx.x;
    const int t = threadIdx.x;
    const int s0 = g_off[n], s1 = g_off[n + 1];
    float num = 0.f, den = 0.f, es = 0.f, esq = 0.f;
    for (int j = s0; j < s1; j++) {
        int2 p = g_perm[j];
        float x = g_eij[(size_t)p.x * DD + t];
        float sg = 1.f / (1.f + __expf(-x));
        num = fmaf(sg, g_Bh[(size_t)p.y * DD + t], num);
        den += sg;
        es += x; esq = fmaf(x, x, esq);
    }
    float hn = g_Ah[(size_t)n * DD + t] + num / (den + 1e-6f);
    g_hnew[(size_t)n * DD + t] = hn;
    int sl = n & 63;
    atomicAdd(&g_slab[0][sl][t], es);
    atomicAdd(&g_slab[1][sl][t], esq);
}

__global__ void k_ered() {
    int t = threadIdx.x;
    float a = 0.f, b = 0.f;
    for (int j = 0; j < 64; j++) { a += g_slab[0][j][t]; b += g_slab[1][j][t]; }
    g_sum_e[t] = a; g_sumsq_e[t] = b;
}

__global__ void k_hstats() {
    const int t = threadIdx.x;
    const int r0 = blockIdx.x * 250;
    float a = 0.f, b = 0.f;
    for (int r = r0; r < r0 + 250; r++) {
        float v = g_hnew[(size_t)r * DD + t];
        a += v; b = fmaf(v, v, b);
    }
    atomicAdd(&g_sum_h[t], a);
    atomicAdd(&g_sumsq_h[t], b);
}

// ---------------- outputs: relu(BN(x)) ----------------------------------------
__global__ void k_hout(const float* __restrict__ gamma, const float* __restrict__ beta,
                       float* __restrict__ out) {
    __shared__ float sM[DD], sS[DD], sB[DD];
    const int t = threadIdx.x;
    if (t < DD) {
        float mean = g_sum_h[t] * (1.f / NN);
        float var  = g_sumsq_h[t] * (1.f / NN) - mean * mean;
        sM[t] = mean; sS[t] = gamma[t] * rsqrtf(var + 1e-5f); sB[t] = beta[t];
    }
    __syncthreads();
    int i4 = blockIdx.x * 256 + t;
    if (i4 < NN * 32) {
        float4 x = ((const float4*)g_hnew)[i4];
        int c = (i4 & 31) * 4;
        float4 o;
        o.x = fmaxf(0.f, (x.x - sM[c+0]) * sS[c+0] + sB[c+0]);
        o.y = fmaxf(0.f, (x.y - sM[c+1]) * sS[c+1] + sB[c+1]);
        o.z = fmaxf(0.f, (x.z - sM[c+2]) * sS[c+2] + sB[c+2]);
        o.w = fmaxf(0.f, (x.w - sM[c+3]) * sS[c+3] + sB[c+3]);
        ((float4*)out)[i4] = o;
    }
}

__global__ void k_eout(const float* __restrict__ gamma, const float* __restrict__ beta,
                       float* __restrict__ out) {
    __shared__ float sM[DD], sS[DD], sB[DD];
    const int t = threadIdx.x;
    if (t < DD) {
        float mean = g_sum_e[t] * (1.f / NE);
        float var  = g_sumsq_e[t] * (1.f / NE) - mean * mean;
        sM[t] = mean; sS[t] = gamma[t] * rsqrtf(var + 1e-5f); sB[t] = beta[t];
    }
    __syncthreads();
    size_t i4 = (size_t)blockIdx.x * 256 + t;
    if (i4 < (size_t)NE * 32) {
        float4 x = ((const float4*)g_eij)[i4];
        int c = (i4 & 31) * 4;
        float4 o;
        o.x = fmaxf(0.f, (x.x - sM[c+0]) * sS[c+0] + sB[c+0]);
        o.y = fmaxf(0.f, (x.y - sM[c+1]) * sS[c+1] + sB[c+1]);
        o.z = fmaxf(0.f, (x.z - sM[c+2]) * sS[c+2] + sB[c+2]);
        o.w = fmaxf(0.f, (x.w - sM[c+3]) * sS[c+3] + sB[c+3]);
        ((float4*)out)[i4] = o;
    }
}

// ---------------- launch ------------------------------------------------------
extern "C" void kernel_launch(void* const* d_in, const int* in_sizes, int n_in,
                              void* d_out, int out_size) {
    const float* h   = (const float*)d_in[0];
    const float* e   = (const float*)d_in[1];
    const int*   src = (const int*)  d_in[2];
    const int*   dst = (const int*)  d_in[3];
    const float* WA  = (const float*)d_in[4];  const float* bA = (const float*)d_in[5];
    const float* WB  = (const float*)d_in[6];  const float* bB = (const float*)d_in[7];
    const float* WC  = (const float*)d_in[8];  const float* bC = (const float*)d_in[9];
    const float* WD  = (const float*)d_in[10]; const float* bD = (const float*)d_in[11];
    const float* WE  = (const float*)d_in[12]; const float* bE = (const float*)d_in[13];
    const float* gamma_h = (const float*)d_in[14]; const float* beta_h = (const float*)d_in[15];
    const float* gamma_e = (const float*)d_in[16]; const float* beta_e = (const float*)d_in[17];
    float* out = (float*)d_out;

    cudaFuncSetAttribute(k_node_hmma, cudaFuncAttributeMaxDynamicSharedMemorySize, SM_NODE_TOTAL);
    cudaFuncSetAttribute(k_edge_hmma, cudaFuncAttributeMaxDynamicSharedMemorySize, SM_EDGE_TOTAL);

    k_init<<<(NN + 255) / 256, 256>>>();
    k_prep_w<<<dim3(64, 5), 256>>>(WA, WB, WC, WD, WE);
    k_node_hmma<<<NT_NODE, 512, SM_NODE_TOTAL>>>(h, bA, bB, bD, bE);
    k_edge_hmma<<<EGRID, 512, SM_EDGE_TOTAL>>>(e, bC, src, dst);
    k_scan1<<<49, 1024>>>();
    k_scan2<<<1, 1>>>();
    k_scan3<<<(NN + 255) / 256, 256>>>();
    k_scatter<<<(NE + 255) / 256, 256>>>(src, dst);
    k_gather<<<NN, 128>>>();
    k_ered<<<1, 128>>>();
    k_hstats<<<200, 128>>>();
    k_hout<<<(NN * 32 + 255) / 256, 256>>>(gamma_h, beta_h, out);
    k_eout<<<(int)(((size_t)NE * 32 + 255) / 256), 256>>>(gamma_e, beta_e, out + (size_t)NN * DD);
}

// round 7
// speedup vs baseline: 1.5002x; 1.1150x over previous
#include <cuda_runtime.h>
#include <cuda_bf16.h>
#include <stdint.h>
#include <math.h>

#define NN 50000
#define NE 800000
#define DD 128
#define NT_NODE 391
#define NT_EDGE 6250
#define EGRID 148

// ---------------- device scratch ---------------------------------------------
__device__ float g_Ah[NN*DD];
__device__ float g_Bh[NN*DD];
__device__ float g_Dh[NN*DD];
__device__ float g_Eh[NN*DD];
__device__ float g_eij[(size_t)NE*DD];     // holds Ce + bias only
__device__ float g_hnew[NN*DD];
__device__ int   g_deg[NN];
__device__ int   g_off[NN+1];
__device__ int   g_cur[NN];
__device__ int2  g_perm[NE];
__device__ float g_sum_e[DD], g_sumsq_e[DD], g_sum_h[DD], g_sumsq_h[DD];
__device__ int   g_bsum[64], g_boff[64];
__device__ float g_slab[2][64][DD];
__device__ __nv_bfloat16 g_WHi[5*16384];
__device__ __nv_bfloat16 g_WLo[5*16384];

// smem layout (bytes): bias | Whi | Wlo | A buffers (rows padded to 136 bf16)
#define SM_BIAS 0
#define SM_WHI  512
#define SM_WLO  35328
#define SM_A0   70144
#define SM_A1   139776
#define SM_EDGE_TOTAL 209408
#define SM_NODE_TOTAL 139776
#define RS 68   // row stride in 32-bit words (136 bf16)

__device__ __forceinline__ void mma16816(float* c, const uint32_t* a, const uint32_t* b) {
    asm volatile("mma.sync.aligned.m16n8k16.row.col.f32.bf16.bf16.f32 "
        "{%0,%1,%2,%3}, {%4,%5,%6,%7}, {%8,%9}, {%0,%1,%2,%3};"
        : "+f"(c[0]), "+f"(c[1]), "+f"(c[2]), "+f"(c[3])
        : "r"(a[0]), "r"(a[1]), "r"(a[2]), "r"(a[3]), "r"(b[0]), "r"(b[1]));
}

// ---------------- small kernels -----------------------------------------------
__global__ void k_init() {
    int i = blockIdx.x * 256 + threadIdx.x;
    if (i < NN) g_deg[i] = 0;
    if (i < DD) { g_sum_e[i] = 0.f; g_sumsq_e[i] = 0.f; g_sum_h[i] = 0.f; g_sumsq_h[i] = 0.f; }
    if (i < 2*64*DD) ((float*)g_slab)[i] = 0.f;
}

__global__ void k_deg(const int* __restrict__ dst) {
    int i = blockIdx.x * 256 + threadIdx.x;
    if (i < NE) atomicAdd(&g_deg[dst[i]], 1);
}

__global__ void k_prep_w(const float* __restrict__ WA, const float* __restrict__ WB,
                         const float* __restrict__ WC, const float* __restrict__ WD,
                         const float* __restrict__ WE) {
    const float* Ws[5] = {WA, WB, WC, WD, WE};
    int mat = blockIdx.y;
    int i = blockIdx.x * 256 + threadIdx.x;
    int n = i >> 7, k = i & 127;
    float x = Ws[mat][k * 128 + n];           // transpose: B[n][k] = W[k][n]
    __nv_bfloat16 hb = __float2bfloat16(x);
    __nv_bfloat16 lb = __float2bfloat16(x - __bfloat162float(hb));
    g_WHi[mat * 16384 + i] = hb;
    g_WLo[mat * 16384 + i] = lb;
}

// ---------------- conversion helpers ------------------------------------------
__device__ __forceinline__ void split4(float4 x, uint2& hi, uint2& lo) {
    __nv_bfloat162 h01 = __floats2bfloat162_rn(x.x, x.y);
    __nv_bfloat162 h23 = __floats2bfloat162_rn(x.z, x.w);
    float l0 = x.x - __bfloat162float(__low2bfloat16(h01));
    float l1 = x.y - __bfloat162float(__high2bfloat16(h01));
    float l2 = x.z - __bfloat162float(__low2bfloat16(h23));
    float l3 = x.w - __bfloat162float(__high2bfloat16(h23));
    __nv_bfloat162 q01 = __floats2bfloat162_rn(l0, l1);
    __nv_bfloat162 q23 = __floats2bfloat162_rn(l2, l3);
    hi = make_uint2(*(uint32_t*)&h01, *(uint32_t*)&h23);
    lo = make_uint2(*(uint32_t*)&q01, *(uint32_t*)&q23);
}

template<bool GUARD>
__device__ __forceinline__ void conv_tile(const float* __restrict__ src, int rowBase,
                                          char* dstA, int t) {
    __nv_bfloat16* sHi = (__nv_bfloat16*)dstA;
    __nv_bfloat16* sLo = (__nv_bfloat16*)(dstA + 34816);
    #pragma unroll
    for (int i = 0; i < 8; i++) {
        int idx = t + i * 512;
        int r = idx >> 5, cg = (idx & 31) << 2;
        float4 x;
        if (GUARD && (rowBase + r >= NN)) x = make_float4(0.f, 0.f, 0.f, 0.f);
        else x = *(const float4*)(src + (size_t)(rowBase + r) * DD + cg);
        uint2 hi, lo;
        split4(x, hi, lo);
        int off = r * 136 + cg;
        *(uint2*)(sHi + off) = hi;
        *(uint2*)(sLo + off) = lo;
    }
}

__device__ __forceinline__ void load_w(char* sm_, int mat, const float* __restrict__ bias, int t) {
    const uint4* wh = (const uint4*)(g_WHi + mat * 16384);
    const uint4* wl = (const uint4*)(g_WLo + mat * 16384);
    __nv_bfloat16* dh = (__nv_bfloat16*)(sm_ + SM_WHI);
    __nv_bfloat16* dl = (__nv_bfloat16*)(sm_ + SM_WLO);
    #pragma unroll
    for (int i = t; i < 2048; i += 512) {
        int n = i >> 4, kg = i & 15;
        *(uint4*)(dh + n * 136 + kg * 8) = wh[i];
        *(uint4*)(dl + n * 136 + kg * 8) = wl[i];
    }
    if (t < 128) ((float*)(sm_ + SM_BIAS))[t] = bias[t];
}

// ---------------- warp GEMM (warp tile 32x32) ---------------------------------
__device__ __forceinline__ void warp_pass(const uint32_t* __restrict__ sA,
                                          const uint32_t* __restrict__ sB,
                                          float acc[2][4][4], int rm, int cn, int lane) {
    int g = lane >> 2, tq = lane & 3;
    #pragma unroll
    for (int s = 0; s < 8; s++) {
        uint32_t a[2][4];
        #pragma unroll
        for (int mt = 0; mt < 2; mt++) {
            const uint32_t* p0 = sA + (rm + mt * 16 + g) * RS + s * 8 + tq;
            const uint32_t* p1 = p0 + 8 * RS;
            a[mt][0] = p0[0]; a[mt][1] = p1[0]; a[mt][2] = p0[4]; a[mt][3] = p1[4];
        }
        uint32_t b[4][2];
        #pragma unroll
        for (int nt = 0; nt < 4; nt++) {
            const uint32_t* p = sB + (cn + nt * 8 + g) * RS + s * 8 + tq;
            b[nt][0] = p[0]; b[nt][1] = p[4];
        }
        #pragma unroll
        for (int mt = 0; mt < 2; mt++)
            #pragma unroll
            for (int nt = 0; nt < 4; nt++)
                mma16816(acc[mt][nt], a[mt], b[nt]);
    }
}

__device__ __forceinline__ void compute_tile(char* sm_, char* aBuf, float acc[2][4][4],
                                             int rm, int cn, int lane) {
    #pragma unroll
    for (int mt = 0; mt < 2; mt++)
        #pragma unroll
        for (int nt = 0; nt < 4; nt++)
            #pragma unroll
            for (int q = 0; q < 4; q++) acc[mt][nt][q] = 0.f;
    const uint32_t* aHi = (const uint32_t*)aBuf;
    const uint32_t* aLo = (const uint32_t*)(aBuf + 34816);
    const uint32_t* wHi = (const uint32_t*)(sm_ + SM_WHI);
    const uint32_t* wLo = (const uint32_t*)(sm_ + SM_WLO);
    warp_pass(aHi, wHi, acc, rm, cn, lane);
    warp_pass(aHi, wLo, acc, rm, cn, lane);
    warp_pass(aLo, wHi, acc, rm, cn, lane);
}

// ---------------- node GEMM: Ah,Bh,Dh,Eh --------------------------------------
__global__ void __launch_bounds__(512, 1) k_node_hmma(
    const float* __restrict__ h,
    const float* __restrict__ bA, const float* __restrict__ bB,
    const float* __restrict__ bD, const float* __restrict__ bE)
{
    extern __shared__ char sm_[];
    const int t = threadIdx.x, lane = t & 31, w = t >> 5;
    const int rm = (w & 3) * 32, cn = (w >> 2) * 32;
    const int rowBase = blockIdx.x * 128;
    const float* sBias = (const float*)(sm_ + SM_BIAS);

    conv_tile<true>(h, rowBase, sm_ + SM_A0, t);

    const float* const biases[4] = {bA, bB, bD, bE};
    float* const outs[4] = {g_Ah, g_Bh, g_Dh, g_Eh};
    const int img[4] = {0, 1, 3, 4};

    for (int mat = 0; mat < 4; mat++) {
        __syncthreads();
        load_w(sm_, img[mat], biases[mat], t);
        __syncthreads();
        float acc[2][4][4];
        compute_tile(sm_, sm_ + SM_A0, acc, rm, cn, lane);
        int g = lane >> 2, tq = lane & 3;
        float* out = outs[mat];
        #pragma unroll
        for (int mt = 0; mt < 2; mt++) {
            #pragma unroll
            for (int half = 0; half < 2; half++) {
                int row = rowBase + rm + mt * 16 + half * 8 + g;
                if (row < NN) {
                    #pragma unroll
                    for (int nt = 0; nt < 4; nt++) {
                        int col = cn + nt * 8 + tq * 2;
                        float2 v;
                        v.x = acc[mt][nt][half * 2 + 0] + sBias[col];
                        v.y = acc[mt][nt][half * 2 + 1] + sBias[col + 1];
                        *(float2*)(out + (size_t)row * DD + col) = v;
                    }
                }
            }
        }
    }
}

// ---------------- edge GEMM (pure: Ce = e@WC + bC) ----------------------------
__global__ void __launch_bounds__(512, 1) k_edge_hmma(
    const float* __restrict__ e, const float* __restrict__ bC)
{
    extern __shared__ char sm_[];
    const int t = threadIdx.x, lane = t & 31, w = t >> 5;
    const int rm = (w & 3) * 32, cn = (w >> 2) * 32;
    const float* sBias = (const float*)(sm_ + SM_BIAS);

    load_w(sm_, 2, bC, t);
    int tile = blockIdx.x;
    if (tile < NT_EDGE) conv_tile<false>(e, tile * 128, sm_ + SM_A0, t);
    __syncthreads();

    int par = 0;
    for (; tile < NT_EDGE; tile += EGRID) {
        int nextTile = tile + EGRID;
        bool hasNext = nextTile < NT_EDGE;
        float4 pf[8];
        if (hasNext) {
            #pragma unroll
            for (int i = 0; i < 8; i++) {
                int idx = t + i * 512;
                pf[i] = *(const float4*)(e + (size_t)(nextTile * 128 + (idx >> 5)) * DD + ((idx & 31) << 2));
            }
        }
        float acc[2][4][4];
        compute_tile(sm_, sm_ + (par ? SM_A1 : SM_A0), acc, rm, cn, lane);
        // epilogue: bias + coalesced store only
        {
            int g = lane >> 2, tq = lane & 3;
            int rowBase = tile * 128;
            #pragma unroll
            for (int mt = 0; mt < 2; mt++) {
                #pragma unroll
                for (int half = 0; half < 2; half++) {
                    int row = rowBase + rm + mt * 16 + half * 8 + g;
                    float* op = g_eij + (size_t)row * DD;
                    #pragma unroll
                    for (int nt = 0; nt < 4; nt++) {
                        int col = cn + nt * 8 + tq * 2;
                        float2 v;
                        v.x = acc[mt][nt][half * 2 + 0] + sBias[col];
                        v.y = acc[mt][nt][half * 2 + 1] + sBias[col + 1];
                        *(float2*)(op + col) = v;
                    }
                }
            }
        }
        if (hasNext) {
            char* dstA = sm_ + (par ? SM_A0 : SM_A1);
            __nv_bfloat16* sHi = (__nv_bfloat16*)dstA;
            __nv_bfloat16* sLo = (__nv_bfloat16*)(dstA + 34816);
            #pragma unroll
            for (int i = 0; i < 8; i++) {
                int idx = t + i * 512;
                int r = idx >> 5, cg = (idx & 31) << 2;
                uint2 hi, lo;
                split4(pf[i], hi, lo);
                int off = r * 136 + cg;
                *(uint2*)(sHi + off) = hi;
                *(uint2*)(sLo + off) = lo;
            }
        }
        __syncthreads();
        par ^= 1;
    }
}

// ---------------- hierarchical scan -------------------------------------------
__global__ void k_scan1() {
    __shared__ int sbuf[1024];
    const int t = threadIdx.x;
    int gidx = blockIdx.x * 1024 + t;
    int v = (gidx < NN) ? g_deg[gidx] : 0;
    sbuf[t] = v;
    __syncthreads();
    for (int d = 1; d < 1024; d <<= 1) {
        int x = (t >= d) ? sbuf[t - d] : 0;
        __syncthreads();
        sbuf[t] += x;
        __syncthreads();
    }
    if (gidx < NN) g_off[gidx] = sbuf[t] - v;
    if (t == 1023) g_bsum[blockIdx.x] = sbuf[1023];
}
__global__ void k_scan2() {
    int a = 0;
    for (int b = 0; b < 49; b++) { g_boff[b] = a; a += g_bsum[b]; }
    g_off[NN] = a;
}
__global__ void k_scan3() {
    int gidx = blockIdx.x * 256 + threadIdx.x;
    if (gidx < NN) {
        int o = g_off[gidx] + g_boff[gidx >> 10];
        g_off[gidx] = o;
        g_cur[gidx] = o;
    }
}

__global__ void k_scatter(const int* __restrict__ src, const int* __restrict__ dst) {
    int i = blockIdx.x * 256 + threadIdx.x;
    if (i < NE) {
        int d = dst[i];
        int pos = atomicAdd(&g_cur[d], 1);
        g_perm[pos] = make_int2(i, src[i]);
    }
}

// ---------------- gather: h_new + e-BN stats (recomputes e_ij) -----------------
__global__ void k_gather() {
    const int n = blockIdx.x;
    const int t = threadIdx.x;
    const int s0 = g_off[n], s1 = g_off[n + 1];
    const float eh = g_Eh[(size_t)n * DD + t];
    float num = 0.f, den = 0.f, es = 0.f, esq = 0.f;
    for (int j = s0; j < s1; j++) {
        int2 p = g_perm[j];
        float x = g_eij[(size_t)p.x * DD + t] + g_Dh[(size_t)p.y * DD + t] + eh;
        float sg = 1.f / (1.f + __expf(-x));
        num = fmaf(sg, g_Bh[(size_t)p.y * DD + t], num);
        den += sg;
        es += x; esq = fmaf(x, x, esq);
    }
    float hn = g_Ah[(size_t)n * DD + t] + num / (den + 1e-6f);
    g_hnew[(size_t)n * DD + t] = hn;
    int sl = n & 63;
    atomicAdd(&g_slab[0][sl][t], es);
    atomicAdd(&g_slab[1][sl][t], esq);
}

__global__ void k_ered() {
    int t = threadIdx.x;
    float a = 0.f, b = 0.f;
    for (int j = 0; j < 64; j++) { a += g_slab[0][j][t]; b += g_slab[1][j][t]; }
    g_sum_e[t] = a; g_sumsq_e[t] = b;
}

__global__ void k_hstats() {
    const int t = threadIdx.x;
    const int r0 = blockIdx.x * 250;
    float a = 0.f, b = 0.f;
    for (int r = r0; r < r0 + 250; r++) {
        float v = g_hnew[(size_t)r * DD + t];
        a += v; b = fmaf(v, v, b);
    }
    atomicAdd(&g_sum_h[t], a);
    atomicAdd(&g_sumsq_h[t], b);
}

// ---------------- outputs: relu(BN(x)) ----------------------------------------
__global__ void k_hout(const float* __restrict__ gamma, const float* __restrict__ beta,
                       float* __restrict__ out) {
    __shared__ float sM[DD], sS[DD], sB[DD];
    const int t = threadIdx.x;
    if (t < DD) {
        float mean = g_sum_h[t] * (1.f / NN);
        float var  = g_sumsq_h[t] * (1.f / NN) - mean * mean;
        sM[t] = mean; sS[t] = gamma[t] * rsqrtf(var + 1e-5f); sB[t] = beta[t];
    }
    __syncthreads();
    int i4 = blockIdx.x * 256 + t;
    if (i4 < NN * 32) {
        float4 x = ((const float4*)g_hnew)[i4];
        int c = (i4 & 31) * 4;
        float4 o;
        o.x = fmaxf(0.f, (x.x - sM[c+0]) * sS[c+0] + sB[c+0]);
        o.y = fmaxf(0.f, (x.y - sM[c+1]) * sS[c+1] + sB[c+1]);
        o.z = fmaxf(0.f, (x.z - sM[c+2]) * sS[c+2] + sB[c+2]);
        o.w = fmaxf(0.f, (x.w - sM[c+3]) * sS[c+3] + sB[c+3]);
        ((float4*)out)[i4] = o;
    }
}

// e_out: recompute x = Ce + Dh[src] + Eh[dst], then relu(BN(x)).
// one warp per edge -> all row reads coalesced, src/dst broadcast.
__global__ void k_eout(const int* __restrict__ src, const int* __restrict__ dst,
                       const float* __restrict__ gamma, const float* __restrict__ beta,
                       float* __restrict__ out) {
    __shared__ float sM[DD], sS[DD], sB[DD];
    const int t = threadIdx.x;
    if (t < DD) {
        float mean = g_sum_e[t] * (1.f / NE);
        float var  = g_sumsq_e[t] * (1.f / NE) - mean * mean;
        sM[t] = mean; sS[t] = gamma[t] * rsqrtf(var + 1e-5f); sB[t] = beta[t];
    }
    __syncthreads();
    int w = t >> 5, lane = t & 31;
    int eg = blockIdx.x * 8 + w;
    if (eg < NE) {
        int s = src[eg], d = dst[eg];
        float4 ce = ((const float4*)(g_eij + (size_t)eg * DD))[lane];
        float4 dv = ((const float4*)(g_Dh  + (size_t)s  * DD))[lane];
        float4 ev = ((const float4*)(g_Eh  + (size_t)d  * DD))[lane];
        int c = lane * 4;
        float4 o;
        float x0 = ce.x + dv.x + ev.x, x1 = ce.y + dv.y + ev.y;
        float x2 = ce.z + dv.z + ev.z, x3 = ce.w + dv.w + ev.w;
        o.x = fmaxf(0.f, (x0 - sM[c+0]) * sS[c+0] + sB[c+0]);
        o.y = fmaxf(0.f, (x1 - sM[c+1]) * sS[c+1] + sB[c+1]);
        o.z = fmaxf(0.f, (x2 - sM[c+2]) * sS[c+2] + sB[c+2]);
        o.w = fmaxf(0.f, (x3 - sM[c+3]) * sS[c+3] + sB[c+3]);
        ((float4*)(out + (size_t)eg * DD))[lane] = o;
    }
}

// ---------------- launch ------------------------------------------------------
extern "C" void kernel_launch(void* const* d_in, const int* in_sizes, int n_in,
                              void* d_out, int out_size) {
    const float* h   = (const float*)d_in[0];
    const float* e   = (const float*)d_in[1];
    const int*   src = (const int*)  d_in[2];
    const int*   dst = (const int*)  d_in[3];
    const float* WA  = (const float*)d_in[4];  const float* bA = (const float*)d_in[5];
    const float* WB  = (const float*)d_in[6];  const float* bB = (const float*)d_in[7];
    const float* WC  = (const float*)d_in[8];  const float* bC = (const float*)d_in[9];
    const float* WD  = (const float*)d_in[10]; const float* bD = (const float*)d_in[11];
    const float* WE  = (const float*)d_in[12]; const float* bE = (const float*)d_in[13];
    const float* gamma_h = (const float*)d_in[14]; const float* beta_h = (const float*)d_in[15];
    const float* gamma_e = (const float*)d_in[16]; const float* beta_e = (const float*)d_in[17];
    float* out = (float*)d_out;

    cudaFuncSetAttribute(k_node_hmma, cudaFuncAttributeMaxDynamicSharedMemorySize, SM_NODE_TOTAL);
    cudaFuncSetAttribute(k_edge_hmma, cudaFuncAttributeMaxDynamicSharedMemorySize, SM_EDGE_TOTAL);

    k_init<<<(NN + 255) / 256, 256>>>();
    k_deg<<<(NE + 255) / 256, 256>>>(dst);
    k_prep_w<<<dim3(64, 5), 256>>>(WA, WB, WC, WD, WE);
    k_scan1<<<49, 1024>>>();
    k_scan2<<<1, 1>>>();
    k_scan3<<<(NN + 255) / 256, 256>>>();
    k_scatter<<<(NE + 255) / 256, 256>>>(src, dst);
    k_node_hmma<<<NT_NODE, 512, SM_NODE_TOTAL>>>(h, bA, bB, bD, bE);
    k_edge_hmma<<<EGRID, 512, SM_EDGE_TOTAL>>>(e, bC);
    k_gather<<<NN, 128>>>();
    k_ered<<<1, 128>>>();
    k_hstats<<<200, 128>>>();
    k_hout<<<(NN * 32 + 255) / 256, 256>>>(gamma_h, beta_h, out);
    k_eout<<<(NE + 7) / 8, 256>>>(src, dst, gamma_e, beta_e, out + (size_t)NN * DD);
}

// round 8
// speedup vs baseline: 1.5269x; 1.0178x over previous
#include <cuda_runtime.h>
#include <cuda_bf16.h>
#include <stdint.h>
#include <math.h>

#define NN 50000
#define NE 800000
#define DD 128
#define NT_NODE 391
#define NT_EDGE64 12500
#define EGRID 296

// ---------------- device scratch ---------------------------------------------
__device__ float g_Ah[NN*DD];
__device__ float g_Bh[NN*DD];
__device__ float g_Dh[NN*DD];
__device__ float g_Eh[NN*DD];
__device__ float g_eij[(size_t)NE*DD];     // Ce + bias only
__device__ float g_hnew[NN*DD];
__device__ int   g_deg[NN];
__device__ int   g_off[NN+1];
__device__ int   g_cur[NN];
__device__ int2  g_perm[NE];
__device__ float g_sum_e[DD], g_sumsq_e[DD], g_sum_h[DD], g_sumsq_h[DD];
__device__ int   g_bsum[64], g_boff[64];
__device__ float g_slab[2][64][DD];
__device__ __nv_bfloat16 g_WHi[5*16384];
__device__ __nv_bfloat16 g_WLo[5*16384];

// node kernel smem layout (128-row tile)
#define SM_BIAS 0
#define SM_WHI  512
#define SM_WLO  35328
#define SM_A0   70144
#define SM_NODE_TOTAL 139776
// edge kernel smem layout (64-row tile): A hi at SM_A0, lo at +17408
#define SM_EDGE_TOTAL 104960
#define RS 68   // row stride in 32-bit words (136 bf16)

__device__ __forceinline__ void mma16816(float* c, const uint32_t* a, const uint32_t* b) {
    asm volatile("mma.sync.aligned.m16n8k16.row.col.f32.bf16.bf16.f32 "
        "{%0,%1,%2,%3}, {%4,%5,%6,%7}, {%8,%9}, {%0,%1,%2,%3};"
        : "+f"(c[0]), "+f"(c[1]), "+f"(c[2]), "+f"(c[3])
        : "r"(a[0]), "r"(a[1]), "r"(a[2]), "r"(a[3]), "r"(b[0]), "r"(b[1]));
}

// ---------------- small kernels -----------------------------------------------
__global__ void k_init() {
    int i = blockIdx.x * 256 + threadIdx.x;
    if (i < NN) g_deg[i] = 0;
    if (i < DD) { g_sum_e[i] = 0.f; g_sumsq_e[i] = 0.f; g_sum_h[i] = 0.f; g_sumsq_h[i] = 0.f; }
    if (i < 2*64*DD) ((float*)g_slab)[i] = 0.f;
}

__global__ void k_deg(const int* __restrict__ dst) {
    int i = blockIdx.x * 256 + threadIdx.x;
    if (i < NE) atomicAdd(&g_deg[dst[i]], 1);
}

__global__ void k_prep_w(const float* __restrict__ WA, const float* __restrict__ WB,
                         const float* __restrict__ WC, const float* __restrict__ WD,
                         const float* __restrict__ WE) {
    const float* Ws[5] = {WA, WB, WC, WD, WE};
    int mat = blockIdx.y;
    int i = blockIdx.x * 256 + threadIdx.x;
    int n = i >> 7, k = i & 127;
    float x = Ws[mat][k * 128 + n];           // transpose: B[n][k] = W[k][n]
    __nv_bfloat16 hb = __float2bfloat16(x);
    __nv_bfloat16 lb = __float2bfloat16(x - __bfloat162float(hb));
    g_WHi[mat * 16384 + i] = hb;
    g_WLo[mat * 16384 + i] = lb;
}

// ---------------- conversion helpers ------------------------------------------
__device__ __forceinline__ void split4(float4 x, uint2& hi, uint2& lo) {
    __nv_bfloat162 h01 = __floats2bfloat162_rn(x.x, x.y);
    __nv_bfloat162 h23 = __floats2bfloat162_rn(x.z, x.w);
    float l0 = x.x - __bfloat162float(__low2bfloat16(h01));
    float l1 = x.y - __bfloat162float(__high2bfloat16(h01));
    float l2 = x.z - __bfloat162float(__low2bfloat16(h23));
    float l3 = x.w - __bfloat162float(__high2bfloat16(h23));
    __nv_bfloat162 q01 = __floats2bfloat162_rn(l0, l1);
    __nv_bfloat162 q23 = __floats2bfloat162_rn(l2, l3);
    hi = make_uint2(*(uint32_t*)&h01, *(uint32_t*)&h23);
    lo = make_uint2(*(uint32_t*)&q01, *(uint32_t*)&q23);
}

// 128-row tile conversion, 512 threads (node kernel)
template<bool GUARD>
__device__ __forceinline__ void conv_tile512(const float* __restrict__ src, int rowBase,
                                             char* dstA, int t) {
    __nv_bfloat16* sHi = (__nv_bfloat16*)dstA;
    __nv_bfloat16* sLo = (__nv_bfloat16*)(dstA + 34816);
    #pragma unroll
    for (int i = 0; i < 8; i++) {
        int idx = t + i * 512;
        int r = idx >> 5, cg = (idx & 31) << 2;
        float4 x;
        if (GUARD && (rowBase + r >= NN)) x = make_float4(0.f, 0.f, 0.f, 0.f);
        else x = *(const float4*)(src + (size_t)(rowBase + r) * DD + cg);
        uint2 hi, lo;
        split4(x, hi, lo);
        int off = r * 136 + cg;
        *(uint2*)(sHi + off) = hi;
        *(uint2*)(sLo + off) = lo;
    }
}

template<int NT>
__device__ __forceinline__ void load_w(char* sm_, int mat, const float* __restrict__ bias, int t) {
    const uint4* wh = (const uint4*)(g_WHi + mat * 16384);
    const uint4* wl = (const uint4*)(g_WLo + mat * 16384);
    __nv_bfloat16* dh = (__nv_bfloat16*)(sm_ + SM_WHI);
    __nv_bfloat16* dl = (__nv_bfloat16*)(sm_ + SM_WLO);
    #pragma unroll
    for (int i = t; i < 2048; i += NT) {
        int n = i >> 4, kg = i & 15;
        *(uint4*)(dh + n * 136 + kg * 8) = wh[i];
        *(uint4*)(dl + n * 136 + kg * 8) = wl[i];
    }
    if (t < 128) ((float*)(sm_ + SM_BIAS))[t] = bias[t];
}

// ---------------- warp GEMM (warp tile 32x32) ---------------------------------
__device__ __forceinline__ void warp_pass(const uint32_t* __restrict__ sA,
                                          const uint32_t* __restrict__ sB,
                                          float acc[2][4][4], int rm, int cn, int lane) {
    int g = lane >> 2, tq = lane & 3;
    #pragma unroll
    for (int s = 0; s < 8; s++) {
        uint32_t a[2][4];
        #pragma unroll
        for (int mt = 0; mt < 2; mt++) {
            const uint32_t* p0 = sA + (rm + mt * 16 + g) * RS + s * 8 + tq;
            const uint32_t* p1 = p0 + 8 * RS;
            a[mt][0] = p0[0]; a[mt][1] = p1[0]; a[mt][2] = p0[4]; a[mt][3] = p1[4];
        }
        uint32_t b[4][2];
        #pragma unroll
        for (int nt = 0; nt < 4; nt++) {
            const uint32_t* p = sB + (cn + nt * 8 + g) * RS + s * 8 + tq;
            b[nt][0] = p[0]; b[nt][1] = p[4];
        }
        #pragma unroll
        for (int mt = 0; mt < 2; mt++)
            #pragma unroll
            for (int nt = 0; nt < 4; nt++)
                mma16816(acc[mt][nt], a[mt], b[nt]);
    }
}

__device__ __forceinline__ void compute_tile(char* sm_, char* aBuf, int aLoOff,
                                             float acc[2][4][4], int rm, int cn, int lane) {
    #pragma unroll
    for (int mt = 0; mt < 2; mt++)
        #pragma unroll
        for (int nt = 0; nt < 4; nt++)
            #pragma unroll
            for (int q = 0; q < 4; q++) acc[mt][nt][q] = 0.f;
    const uint32_t* aHi = (const uint32_t*)aBuf;
    const uint32_t* aLo = (const uint32_t*)(aBuf + aLoOff);
    const uint32_t* wHi = (const uint32_t*)(sm_ + SM_WHI);
    const uint32_t* wLo = (const uint32_t*)(sm_ + SM_WLO);
    warp_pass(aHi, wHi, acc, rm, cn, lane);
    warp_pass(aHi, wLo, acc, rm, cn, lane);
    warp_pass(aLo, wHi, acc, rm, cn, lane);
}

// ---------------- node GEMM: Ah,Bh,Dh,Eh (128-row tiles, 512 thr) --------------
__global__ void __launch_bounds__(512, 1) k_node_hmma(
    const float* __restrict__ h,
    const float* __restrict__ bA, const float* __restrict__ bB,
    const float* __restrict__ bD, const float* __restrict__ bE)
{
    extern __shared__ char sm_[];
    const int t = threadIdx.x, lane = t & 31, w = t >> 5;
    const int rm = (w & 3) * 32, cn = (w >> 2) * 32;
    const int rowBase = blockIdx.x * 128;
    const float* sBias = (const float*)(sm_ + SM_BIAS);

    conv_tile512<true>(h, rowBase, sm_ + SM_A0, t);

    const float* const biases[4] = {bA, bB, bD, bE};
    float* const outs[4] = {g_Ah, g_Bh, g_Dh, g_Eh};
    const int img[4] = {0, 1, 3, 4};

    for (int mat = 0; mat < 4; mat++) {
        __syncthreads();
        load_w<512>(sm_, img[mat], biases[mat], t);
        __syncthreads();
        float acc[2][4][4];
        compute_tile(sm_, sm_ + SM_A0, 34816, acc, rm, cn, lane);
        int g = lane >> 2, tq = lane & 3;
        float* out = outs[mat];
        #pragma unroll
        for (int mt = 0; mt < 2; mt++) {
            #pragma unroll
            for (int half = 0; half < 2; half++) {
                int row = rowBase + rm + mt * 16 + half * 8 + g;
                if (row < NN) {
                    #pragma unroll
                    for (int nt = 0; nt < 4; nt++) {
                        int col = cn + nt * 8 + tq * 2;
                        float2 v;
                        v.x = acc[mt][nt][half * 2 + 0] + sBias[col];
                        v.y = acc[mt][nt][half * 2 + 1] + sBias[col + 1];
                        *(float2*)(out + (size_t)row * DD + col) = v;
                    }
                }
            }
        }
    }
}

// ---------------- edge GEMM: 64-row tiles, 256 thr, 2 CTAs/SM ------------------
__global__ void __launch_bounds__(256, 2) k_edge_hmma(
    const float* __restrict__ e, const float* __restrict__ bC)
{
    extern __shared__ char sm_[];
    const int t = threadIdx.x, lane = t & 31, w = t >> 5;
    const int rm = (w & 1) * 32, cn = (w >> 1) * 32;   // 2 m-groups x 4 n-groups
    const float* sBias = (const float*)(sm_ + SM_BIAS);
    char* aBuf = sm_ + SM_A0;
    __nv_bfloat16* sHi = (__nv_bfloat16*)aBuf;
    __nv_bfloat16* sLo = (__nv_bfloat16*)(aBuf + 17408);

    load_w<256>(sm_, 2, bC, t);

    int tile = blockIdx.x;
    // prologue: load + convert first tile
    if (tile < NT_EDGE64) {
        #pragma unroll
        for (int i = 0; i < 8; i++) {
            int idx = t + i * 256;                  // 2048 float4 = 64 rows
            int r = idx >> 5, cg = (idx & 31) << 2;
            float4 x = *(const float4*)(e + (size_t)(tile * 64 + r) * DD + cg);
            uint2 hi, lo;
            split4(x, hi, lo);
            int off = r * 136 + cg;
            *(uint2*)(sHi + off) = hi;
            *(uint2*)(sLo + off) = lo;
        }
    }
    __syncthreads();

    for (; tile < NT_EDGE64; tile += EGRID) {
        int nextTile = tile + EGRID;
        bool hasNext = nextTile < NT_EDGE64;
        float4 pf[8];
        if (hasNext) {
            #pragma unroll
            for (int i = 0; i < 8; i++) {
                int idx = t + i * 256;
                pf[i] = *(const float4*)(e + (size_t)(nextTile * 64 + (idx >> 5)) * DD + ((idx & 31) << 2));
            }
        }
        float acc[2][4][4];
        compute_tile(sm_, aBuf, 17408, acc, rm, cn, lane);
        // epilogue: bias + coalesced store
        {
            int g = lane >> 2, tq = lane & 3;
            int rowBase = tile * 64;
            #pragma unroll
            for (int mt = 0; mt < 2; mt++) {
                #pragma unroll
                for (int half = 0; half < 2; half++) {
                    int row = rowBase + rm + mt * 16 + half * 8 + g;
                    float* op = g_eij + (size_t)row * DD;
                    #pragma unroll
                    for (int nt = 0; nt < 4; nt++) {
                        int col = cn + nt * 8 + tq * 2;
                        float2 v;
                        v.x = acc[mt][nt][half * 2 + 0] + sBias[col];
                        v.y = acc[mt][nt][half * 2 + 1] + sBias[col + 1];
                        *(float2*)(op + col) = v;
                    }
                }
            }
        }
        __syncthreads();          // all MMAs done reading A
        if (hasNext) {
            #pragma unroll
            for (int i = 0; i < 8; i++) {
                int idx = t + i * 256;
                int r = idx >> 5, cg = (idx & 31) << 2;
                uint2 hi, lo;
                split4(pf[i], hi, lo);
                int off = r * 136 + cg;
                *(uint2*)(sHi + off) = hi;
                *(uint2*)(sLo + off) = lo;
            }
        }
        __syncthreads();
    }
}

// ---------------- hierarchical scan -------------------------------------------
__global__ void k_scan1() {
    __shared__ int sbuf[1024];
    const int t = threadIdx.x;
    int gidx = blockIdx.x * 1024 + t;
    int v = (gidx < NN) ? g_deg[gidx] : 0;
    sbuf[t] = v;
    __syncthreads();
    for (int d = 1; d < 1024; d <<= 1) {
        int x = (t >= d) ? sbuf[t - d] : 0;
        __syncthreads();
        sbuf[t] += x;
        __syncthreads();
    }
    if (gidx < NN) g_off[gidx] = sbuf[t] - v;
    if (t == 1023) g_bsum[blockIdx.x] = sbuf[1023];
}
__global__ void k_scan2() {
    int a = 0;
    for (int b = 0; b < 49; b++) { g_boff[b] = a; a += g_bsum[b]; }
    g_off[NN] = a;
}
__global__ void k_scan3() {
    int gidx = blockIdx.x * 256 + threadIdx.x;
    if (gidx < NN) {
        int o = g_off[gidx] + g_boff[gidx >> 10];
        g_off[gidx] = o;
        g_cur[gidx] = o;
    }
}

__global__ void k_scatter(const int* __restrict__ src, const int* __restrict__ dst) {
    int i = blockIdx.x * 256 + threadIdx.x;
    if (i < NE) {
        int d = dst[i];
        int pos = atomicAdd(&g_cur[d], 1);
        g_perm[pos] = make_int2(i, src[i]);
    }
}

// ---------------- gather: h_new + e-BN stats (recomputes e_ij) -----------------
__global__ void k_gather() {
    const int n = blockIdx.x;
    const int t = threadIdx.x;
    const int s0 = g_off[n], s1 = g_off[n + 1];
    const float eh = g_Eh[(size_t)n * DD + t];
    float num = 0.f, den = 0.f, es = 0.f, esq = 0.f;
    for (int j = s0; j < s1; j++) {
        int2 p = g_perm[j];
        float x = g_eij[(size_t)p.x * DD + t] + g_Dh[(size_t)p.y * DD + t] + eh;
        float sg = 1.f / (1.f + __expf(-x));
        num = fmaf(sg, g_Bh[(size_t)p.y * DD + t], num);
        den += sg;
        es += x; esq = fmaf(x, x, esq);
    }
    float hn = g_Ah[(size_t)n * DD + t] + num / (den + 1e-6f);
    g_hnew[(size_t)n * DD + t] = hn;
    int sl = n & 63;
    atomicAdd(&g_slab[0][sl][t], es);
    atomicAdd(&g_slab[1][sl][t], esq);
}

__global__ void k_ered() {
    int t = threadIdx.x;
    float a = 0.f, b = 0.f;
    for (int j = 0; j < 64; j++) { a += g_slab[0][j][t]; b += g_slab[1][j][t]; }
    g_sum_e[t] = a; g_sumsq_e[t] = b;
}

__global__ void k_hstats() {
    const int t = threadIdx.x;
    const int r0 = blockIdx.x * 250;
    float a = 0.f, b = 0.f;
    for (int r = r0; r < r0 + 250; r++) {
        float v = g_hnew[(size_t)r * DD + t];
        a += v; b = fmaf(v, v, b);
    }
    atomicAdd(&g_sum_h[t], a);
    atomicAdd(&g_sumsq_h[t], b);
}

// ---------------- outputs: relu(BN(x)) ----------------------------------------
__global__ void k_hout(const float* __restrict__ gamma, const float* __restrict__ beta,
                       float* __restrict__ out) {
    __shared__ float sM[DD], sS[DD], sB[DD];
    const int t = threadIdx.x;
    if (t < DD) {
        float mean = g_sum_h[t] * (1.f / NN);
        float var  = g_sumsq_h[t] * (1.f / NN) - mean * mean;
        sM[t] = mean; sS[t] = gamma[t] * rsqrtf(var + 1e-5f); sB[t] = beta[t];
    }
    __syncthreads();
    int i4 = blockIdx.x * 256 + t;
    if (i4 < NN * 32) {
        float4 x = ((const float4*)g_hnew)[i4];
        int c = (i4 & 31) * 4;
        float4 o;
        o.x = fmaxf(0.f, (x.x - sM[c+0]) * sS[c+0] + sB[c+0]);
        o.y = fmaxf(0.f, (x.y - sM[c+1]) * sS[c+1] + sB[c+1]);
        o.z = fmaxf(0.f, (x.z - sM[c+2]) * sS[c+2] + sB[c+2]);
        o.w = fmaxf(0.f, (x.w - sM[c+3]) * sS[c+3] + sB[c+3]);
        ((float4*)out)[i4] = o;
    }
}

__global__ void k_eout(const int* __restrict__ src, const int* __restrict__ dst,
                       const float* __restrict__ gamma, const float* __restrict__ beta,
                       float* __restrict__ out) {
    __shared__ float sM[DD], sS[DD], sB[DD];
    const int t = threadIdx.x;
    if (t < DD) {
        float mean = g_sum_e[t] * (1.f / NE);
        float var  = g_sumsq_e[t] * (1.f / NE) - mean * mean;
        sM[t] = mean; sS[t] = gamma[t] * rsqrtf(var + 1e-5f); sB[t] = beta[t];
    }
    __syncthreads();
    int w = t >> 5, lane = t & 31;
    int eg = blockIdx.x * 8 + w;
    if (eg < NE) {
        int s = src[eg], d = dst[eg];
        float4 ce = ((const float4*)(g_eij + (size_t)eg * DD))[lane];
        float4 dv = ((const float4*)(g_Dh  + (size_t)s  * DD))[lane];
        float4 ev = ((const float4*)(g_Eh  + (size_t)d  * DD))[lane];
        int c = lane * 4;
        float4 o;
        float x0 = ce.x + dv.x + ev.x, x1 = ce.y + dv.y + ev.y;
        float x2 = ce.z + dv.z + ev.z, x3 = ce.w + dv.w + ev.w;
        o.x = fmaxf(0.f, (x0 - sM[c+0]) * sS[c+0] + sB[c+0]);
        o.y = fmaxf(0.f, (x1 - sM[c+1]) * sS[c+1] + sB[c+1]);
        o.z = fmaxf(0.f, (x2 - sM[c+2]) * sS[c+2] + sB[c+2]);
        o.w = fmaxf(0.f, (x3 - sM[c+3]) * sS[c+3] + sB[c+3]);
        ((float4*)(out + (size_t)eg * DD))[lane] = o;
    }
}

// ---------------- launch ------------------------------------------------------
extern "C" void kernel_launch(void* const* d_in, const int* in_sizes, int n_in,
                              void* d_out, int out_size) {
    const float* h   = (const float*)d_in[0];
    const float* e   = (const float*)d_in[1];
    const int*   src = (const int*)  d_in[2];
    const int*   dst = (const int*)  d_in[3];
    const float* WA  = (const float*)d_in[4];  const float* bA = (const float*)d_in[5];
    const float* WB  = (const float*)d_in[6];  const float* bB = (const float*)d_in[7];
    const float* WC  = (const float*)d_in[8];  const float* bC = (const float*)d_in[9];
    const float* WD  = (const float*)d_in[10]; const float* bD = (const float*)d_in[11];
    const float* WE  = (const float*)d_in[12]; const float* bE = (const float*)d_in[13];
    const float* gamma_h = (const float*)d_in[14]; const float* beta_h = (const float*)d_in[15];
    const float* gamma_e = (const float*)d_in[16]; const float* beta_e = (const float*)d_in[17];
    float* out = (float*)d_out;

    cudaFuncSetAttribute(k_node_hmma, cudaFuncAttributeMaxDynamicSharedMemorySize, SM_NODE_TOTAL);
    cudaFuncSetAttribute(k_edge_hmma, cudaFuncAttributeMaxDynamicSharedMemorySize, SM_EDGE_TOTAL);

    k_init<<<(NN + 255) / 256, 256>>>();
    k_deg<<<(NE + 255) / 256, 256>>>(dst);
    k_prep_w<<<dim3(64, 5), 256>>>(WA, WB, WC, WD, WE);
    k_scan1<<<49, 1024>>>();
    k_scan2<<<1, 1>>>();
    k_scan3<<<(NN + 255) / 256, 256>>>();
    k_scatter<<<(NE + 255) / 256, 256>>>(src, dst);
    k_node_hmma<<<NT_NODE, 512, SM_NODE_TOTAL>>>(h, bA, bB, bD, bE);
    k_edge_hmma<<<EGRID, 256, SM_EDGE_TOTAL>>>(e, bC);
    k_gather<<<NN, 128>>>();
    k_ered<<<1, 128>>>();
    k_hstats<<<200, 128>>>();
    k_hout<<<(NN * 32 + 255) / 256, 256>>>(gamma_h, beta_h, out);
    k_eout<<<(NE + 7) / 8, 256>>>(src, dst, gamma_e, beta_e, out + (size_t)NN * DD);
}

// round 9
// speedup vs baseline: 2.2534x; 1.4758x over previous
#include <cuda_runtime.h>
#include <cuda_bf16.h>
#include <stdint.h>
#include <math.h>

#define NN 50000
#define NE 800000
#define DD 128
#define NT_NODE 391
#define NT_EDGE 6250
#define EGRID 148

// ---------------- device scratch ---------------------------------------------
__device__ float g_Ah[NN*DD];
__device__ float g_Bh[NN*DD];
__device__ float g_Dh[NN*DD];
__device__ float g_Eh[NN*DD];
__device__ float g_eij[(size_t)NE*DD];     // Ce + bias only
__device__ float g_hnew[NN*DD];
__device__ int   g_deg[NN];
__device__ int   g_off[NN+1];
__device__ int   g_cur[NN];
__device__ int2  g_perm[NE];
__device__ float g_sum_e[DD], g_sumsq_e[DD], g_sum_h[DD], g_sumsq_h[DD];
__device__ int   g_bsum[64], g_boff[64];
__device__ float g_slab[2][64][DD];        // e stats slabs
__device__ float g_slabh[2][64][DD];       // h stats slabs
__device__ __nv_bfloat16 g_WHi[5*16384];
__device__ __nv_bfloat16 g_WLo[5*16384];

// smem layout (bytes): bias | Whi | Wlo | A f32 buffers (rows padded to 132 f32)
#define SM_BIAS 0
#define SM_WHI  512
#define SM_WLO  35328
#define SM_A0   70144
#define SM_A1   137728
#define SM_EDGE_TOTAL 205312
#define SM_NODE_TOTAL 137728
#define RS  68    // W row stride in 32-bit words (136 bf16)
#define RSF 132   // A row stride in f32

__device__ __forceinline__ void mma16816(float* c, const uint32_t* a, const uint32_t* b) {
    asm volatile("mma.sync.aligned.m16n8k16.row.col.f32.bf16.bf16.f32 "
        "{%0,%1,%2,%3}, {%4,%5,%6,%7}, {%8,%9}, {%0,%1,%2,%3};"
        : "+f"(c[0]), "+f"(c[1]), "+f"(c[2]), "+f"(c[3])
        : "r"(a[0]), "r"(a[1]), "r"(a[2]), "r"(a[3]), "r"(b[0]), "r"(b[1]));
}

__device__ __forceinline__ uint32_t smem_u32(const void* p) {
    uint32_t a;
    asm("{ .reg .u64 t; cvta.to.shared.u64 t, %1; cvt.u32.u64 %0, t; }" : "=r"(a) : "l"(p));
    return a;
}

__device__ __forceinline__ void split2(float2 v, uint32_t& hi, uint32_t& lo) {
    __nv_bfloat162 h = __floats2bfloat162_rn(v.x, v.y);
    float hx = __bfloat162float(__low2bfloat16(h));
    float hy = __bfloat162float(__high2bfloat16(h));
    __nv_bfloat162 l = __floats2bfloat162_rn(v.x - hx, v.y - hy);
    hi = *(uint32_t*)&h; lo = *(uint32_t*)&l;
}

// ---------------- small kernels -----------------------------------------------
__global__ void k_init() {
    int i = blockIdx.x * 256 + threadIdx.x;
    if (i < NN) g_deg[i] = 0;
    if (i < DD) { g_sum_e[i] = 0.f; g_sumsq_e[i] = 0.f; g_sum_h[i] = 0.f; g_sumsq_h[i] = 0.f; }
    if (i < 2*64*DD) { ((float*)g_slab)[i] = 0.f; ((float*)g_slabh)[i] = 0.f; }
}

__global__ void k_deg(const int* __restrict__ dst) {
    int i = blockIdx.x * 256 + threadIdx.x;
    if (i < NE) atomicAdd(&g_deg[dst[i]], 1);
}

__global__ void k_prep_w(const float* __restrict__ WA, const float* __restrict__ WB,
                         const float* __restrict__ WC, const float* __restrict__ WD,
                         const float* __restrict__ WE) {
    const float* Ws[5] = {WA, WB, WC, WD, WE};
    int mat = blockIdx.y;
    int i = blockIdx.x * 256 + threadIdx.x;
    int n = i >> 7, k = i & 127;
    float x = Ws[mat][k * 128 + n];           // transpose: B[n][k] = W[k][n]
    __nv_bfloat16 hb = __float2bfloat16(x);
    __nv_bfloat16 lb = __float2bfloat16(x - __bfloat162float(hb));
    g_WHi[mat * 16384 + i] = hb;
    g_WLo[mat * 16384 + i] = lb;
}

template<int NT>
__device__ __forceinline__ void load_w(char* sm_, int mat, const float* __restrict__ bias, int t) {
    const uint4* wh = (const uint4*)(g_WHi + mat * 16384);
    const uint4* wl = (const uint4*)(g_WLo + mat * 16384);
    __nv_bfloat16* dh = (__nv_bfloat16*)(sm_ + SM_WHI);
    __nv_bfloat16* dl = (__nv_bfloat16*)(sm_ + SM_WLO);
    #pragma unroll
    for (int i = t; i < 2048; i += NT) {
        int n = i >> 4, kg = i & 15;
        *(uint4*)(dh + n * 136 + kg * 8) = wh[i];
        *(uint4*)(dl + n * 136 + kg * 8) = wl[i];
    }
    if (t < 128) ((float*)(sm_ + SM_BIAS))[t] = bias[t];
}

// ---------------- fused 3-term compute from f32 A smem -------------------------
__device__ __forceinline__ void compute_f32(const float* __restrict__ aF, const char* sm_,
                                            float acc[2][4][4], int rm, int cn, int lane) {
    #pragma unroll
    for (int mt = 0; mt < 2; mt++)
        #pragma unroll
        for (int nt = 0; nt < 4; nt++)
            #pragma unroll
            for (int q = 0; q < 4; q++) acc[mt][nt][q] = 0.f;
    const uint32_t* wHi = (const uint32_t*)(sm_ + SM_WHI);
    const uint32_t* wLo = (const uint32_t*)(sm_ + SM_WLO);
    int g = lane >> 2, tq = lane & 3;
    #pragma unroll
    for (int s = 0; s < 8; s++) {
        uint32_t bH[4][2], bL[4][2];
        #pragma unroll
        for (int nt = 0; nt < 4; nt++) {
            const uint32_t* p = wHi + (cn + nt * 8 + g) * RS + s * 8 + tq;
            bH[nt][0] = p[0]; bH[nt][1] = p[4];
            const uint32_t* q = wLo + (cn + nt * 8 + g) * RS + s * 8 + tq;
            bL[nt][0] = q[0]; bL[nt][1] = q[4];
        }
        #pragma unroll
        for (int mt = 0; mt < 2; mt++) {
            const float* base = aF + (rm + mt * 16 + g) * RSF + s * 16 + 2 * tq;
            float2 q0 = *(const float2*)(base);
            float2 q1 = *(const float2*)(base + 8 * RSF);
            float2 q2 = *(const float2*)(base + 8);
            float2 q3 = *(const float2*)(base + 8 * RSF + 8);
            uint32_t aH[4], aL[4];
            split2(q0, aH[0], aL[0]);
            split2(q1, aH[1], aL[1]);
            split2(q2, aH[2], aL[2]);
            split2(q3, aH[3], aL[3]);
            #pragma unroll
            for (int nt = 0; nt < 4; nt++) {
                mma16816(acc[mt][nt], aH, bH[nt]);
                mma16816(acc[mt][nt], aH, bL[nt]);
                mma16816(acc[mt][nt], aL, bH[nt]);
            }
        }
    }
}

// ---------------- node GEMM: Ah,Bh,Dh,Eh (128-row tiles, 512 thr) --------------
__global__ void __launch_bounds__(512, 1) k_node_hmma(
    const float* __restrict__ h,
    const float* __restrict__ bA, const float* __restrict__ bB,
    const float* __restrict__ bD, const float* __restrict__ bE)
{
    extern __shared__ char sm_[];
    const int t = threadIdx.x, lane = t & 31, w = t >> 5;
    const int rm = (w & 3) * 32, cn = (w >> 2) * 32;
    const int rowBase = blockIdx.x * 128;
    const float* sBias = (const float*)(sm_ + SM_BIAS);
    float* aF = (float*)(sm_ + SM_A0);

    #pragma unroll
    for (int i = 0; i < 8; i++) {
        int idx = t + i * 512;
        int r = idx >> 5, cg = (idx & 31) << 2;
        float4 x = (rowBase + r >= NN) ? make_float4(0.f, 0.f, 0.f, 0.f)
                 : *(const float4*)(h + (size_t)(rowBase + r) * DD + cg);
        *(float4*)(aF + r * RSF + cg) = x;
    }

    const float* const biases[4] = {bA, bB, bD, bE};
    float* const outs[4] = {g_Ah, g_Bh, g_Dh, g_Eh};
    const int img[4] = {0, 1, 3, 4};

    for (int mat = 0; mat < 4; mat++) {
        __syncthreads();
        load_w<512>(sm_, img[mat], biases[mat], t);
        __syncthreads();
        float acc[2][4][4];
        compute_f32(aF, sm_, acc, rm, cn, lane);
        int g = lane >> 2, tq = lane & 3;
        float* out = outs[mat];
        #pragma unroll
        for (int mt = 0; mt < 2; mt++) {
            #pragma unroll
            for (int half = 0; half < 2; half++) {
                int row = rowBase + rm + mt * 16 + half * 8 + g;
                if (row < NN) {
                    #pragma unroll
                    for (int nt = 0; nt < 4; nt++) {
                        int col = cn + nt * 8 + tq * 2;
                        float2 v;
                        v.x = acc[mt][nt][half * 2 + 0] + sBias[col];
                        v.y = acc[mt][nt][half * 2 + 1] + sBias[col + 1];
                        *(float2*)(out + (size_t)row * DD + col) = v;
                    }
                }
            }
        }
    }
}

// ---------------- edge GEMM: cp.async double-buffered, 128-row tiles -----------
__device__ __forceinline__ void issue_tile(const float* __restrict__ e, int tile,
                                           uint32_t sdst, int t) {
    const char* gsrc = (const char*)(e + (size_t)tile * 128 * DD);
    #pragma unroll
    for (int i = 0; i < 8; i++) {
        int idx = t + i * 512;
        int r = idx >> 5, c = idx & 31;
        uint32_t d = sdst + r * (RSF * 4) + c * 16;
        const char* gp = gsrc + r * 512 + c * 16;
        asm volatile("cp.async.cg.shared.global [%0], [%1], 16;" :: "r"(d), "l"(gp));
    }
    asm volatile("cp.async.commit_group;" ::: "memory");
}

__global__ void __launch_bounds__(512, 1) k_edge_hmma(
    const float* __restrict__ e, const float* __restrict__ bC)
{
    extern __shared__ char sm_[];
    const int t = threadIdx.x, lane = t & 31, w = t >> 5;
    const int rm = (w & 3) * 32, cn = (w >> 2) * 32;
    const float* sBias = (const float*)(sm_ + SM_BIAS);
    const uint32_t sA[2] = { smem_u32(sm_ + SM_A0), smem_u32(sm_ + SM_A1) };

    load_w<512>(sm_, 2, bC, t);

    int tile = blockIdx.x;
    if (tile < NT_EDGE) issue_tile(e, tile, sA[0], t);

    int par = 0;
    for (; tile < NT_EDGE; tile += EGRID) {
        int nextTile = tile + EGRID;
        bool hasNext = nextTile < NT_EDGE;
        if (hasNext) issue_tile(e, nextTile, sA[par ^ 1], t);
        if (hasNext) asm volatile("cp.async.wait_group 1;" ::: "memory");
        else         asm volatile("cp.async.wait_group 0;" ::: "memory");
        __syncthreads();

        float acc[2][4][4];
        compute_f32((const float*)(sm_ + (par ? SM_A1 : SM_A0)), sm_, acc, rm, cn, lane);

        {   // epilogue: bias + coalesced store
            int g = lane >> 2, tq = lane & 3;
            int rowBase = tile * 128;
            #pragma unroll
            for (int mt = 0; mt < 2; mt++) {
                #pragma unroll
                for (int half = 0; half < 2; half++) {
                    int row = rowBase + rm + mt * 16 + half * 8 + g;
                    float* op = g_eij + (size_t)row * DD;
                    #pragma unroll
                    for (int nt = 0; nt < 4; nt++) {
                        int col = cn + nt * 8 + tq * 2;
                        float2 v;
                        v.x = acc[mt][nt][half * 2 + 0] + sBias[col];
                        v.y = acc[mt][nt][half * 2 + 1] + sBias[col + 1];
                        *(float2*)(op + col) = v;
                    }
                }
            }
        }
        __syncthreads();      // all warps done reading buf par before next refill
        par ^= 1;
    }
}

// ---------------- hierarchical scan -------------------------------------------
__global__ void k_scan1() {
    __shared__ int sbuf[1024];
    const int t = threadIdx.x;
    int gidx = blockIdx.x * 1024 + t;
    int v = (gidx < NN) ? g_deg[gidx] : 0;
    sbuf[t] = v;
    __syncthreads();
    for (int d = 1; d < 1024; d <<= 1) {
        int x = (t >= d) ? sbuf[t - d] : 0;
        __syncthreads();
        sbuf[t] += x;
        __syncthreads();
    }
    if (gidx < NN) g_off[gidx] = sbuf[t] - v;
    if (t == 1023) g_bsum[blockIdx.x] = sbuf[1023];
}
__global__ void k_scan2() {
    int a = 0;
    for (int b = 0; b < 49; b++) { g_boff[b] = a; a += g_bsum[b]; }
    g_off[NN] = a;
}
__global__ void k_scan3() {
    int gidx = blockIdx.x * 256 + threadIdx.x;
    if (gidx < NN) {
        int o = g_off[gidx] + g_boff[gidx >> 10];
        g_off[gidx] = o;
        g_cur[gidx] = o;
    }
}

__global__ void k_scatter(const int* __restrict__ src, const int* __restrict__ dst) {
    int i = blockIdx.x * 256 + threadIdx.x;
    if (i < NE) {
        int d = dst[i];
        int pos = atomicAdd(&g_cur[d], 1);
        g_perm[pos] = make_int2(i, src[i]);
    }
}

// ---------------- gather: h_new + e-stats + h-stats, 2x unroll -----------------
__global__ void k_gather() {
    const int n = blockIdx.x;
    const int t = threadIdx.x;
    const int s0 = g_off[n], s1 = g_off[n + 1];
    const float eh = g_Eh[(size_t)n * DD + t];
    float num = 0.f, den = 0.f, es = 0.f, esq = 0.f;
    int j = s0;
    for (; j + 2 <= s1; j += 2) {
        int2 p0 = g_perm[j], p1 = g_perm[j + 1];
        float c0 = g_eij[(size_t)p0.x * DD + t];
        float c1 = g_eij[(size_t)p1.x * DD + t];
        float d0 = g_Dh[(size_t)p0.y * DD + t];
        float d1 = g_Dh[(size_t)p1.y * DD + t];
        float b0 = g_Bh[(size_t)p0.y * DD + t];
        float b1 = g_Bh[(size_t)p1.y * DD + t];
        float x0 = c0 + d0 + eh, x1 = c1 + d1 + eh;
        float sg0 = 1.f / (1.f + __expf(-x0));
        float sg1 = 1.f / (1.f + __expf(-x1));
        num = fmaf(sg0, b0, num); num = fmaf(sg1, b1, num);
        den += sg0 + sg1;
        es += x0 + x1;
        esq = fmaf(x0, x0, esq); esq = fmaf(x1, x1, esq);
    }
    if (j < s1) {
        int2 p = g_perm[j];
        float x = g_eij[(size_t)p.x * DD + t] + g_Dh[(size_t)p.y * DD + t] + eh;
        float sg = 1.f / (1.f + __expf(-x));
        num = fmaf(sg, g_Bh[(size_t)p.y * DD + t], num);
        den += sg;
        es += x; esq = fmaf(x, x, esq);
    }
    float hn = g_Ah[(size_t)n * DD + t] + num / (den + 1e-6f);
    g_hnew[(size_t)n * DD + t] = hn;
    int sl = n & 63;
    atomicAdd(&g_slab[0][sl][t], es);
    atomicAdd(&g_slab[1][sl][t], esq);
    atomicAdd(&g_slabh[0][sl][t], hn);
    atomicAdd(&g_slabh[1][sl][t], hn * hn);
}

__global__ void k_red() {
    int t = threadIdx.x;       // 256 threads: t<128 -> e stats, else h stats
    if (t < 128) {
        float a = 0.f, b = 0.f;
        for (int j = 0; j < 64; j++) { a += g_slab[0][j][t]; b += g_slab[1][j][t]; }
        g_sum_e[t] = a; g_sumsq_e[t] = b;
    } else {
        int c = t - 128;
        float a = 0.f, b = 0.f;
        for (int j = 0; j < 64; j++) { a += g_slabh[0][j][c]; b += g_slabh[1][j][c]; }
        g_sum_h[c] = a; g_sumsq_h[c] = b;
    }
}

// ---------------- outputs: relu(BN(x)) ----------------------------------------
__global__ void k_hout(const float* __restrict__ gamma, const float* __restrict__ beta,
                       float* __restrict__ out) {
    __shared__ float sM[DD], sS[DD], sB[DD];
    const int t = threadIdx.x;
    if (t < DD) {
        float mean = g_sum_h[t] * (1.f / NN);
        float var  = g_sumsq_h[t] * (1.f / NN) - mean * mean;
        sM[t] = mean; sS[t] = gamma[t] * rsqrtf(var + 1e-5f); sB[t] = beta[t];
    }
    __syncthreads();
    int i4 = blockIdx.x * 256 + t;
    if (i4 < NN * 32) {
        float4 x = ((const float4*)g_hnew)[i4];
        int c = (i4 & 31) * 4;
        float4 o;
        o.x = fmaxf(0.f, (x.x - sM[c+0]) * sS[c+0] + sB[c+0]);
        o.y = fmaxf(0.f, (x.y - sM[c+1]) * sS[c+1] + sB[c+1]);
        o.z = fmaxf(0.f, (x.z - sM[c+2]) * sS[c+2] + sB[c+2]);
        o.w = fmaxf(0.f, (x.w - sM[c+3]) * sS[c+3] + sB[c+3]);
        ((float4*)out)[i4] = o;
    }
}

// e_out: recompute x = Ce + Dh[src] + Eh[dst], relu(BN(x)); 2 edges per warp.
__global__ void k_eout(const int* __restrict__ src, const int* __restrict__ dst,
                       const float* __restrict__ gamma, const float* __restrict__ beta,
                       float* __restrict__ out) {
    __shared__ float sM[DD], sS[DD], sB[DD];
    const int t = threadIdx.x;
    if (t < DD) {
        float mean = g_sum_e[t] * (1.f / NE);
        float var  = g_sumsq_e[t] * (1.f / NE) - mean * mean;
        sM[t] = mean; sS[t] = gamma[t] * rsqrtf(var + 1e-5f); sB[t] = beta[t];
    }
    __syncthreads();
    int w = t >> 5, lane = t & 31;
    int eg = blockIdx.x * 16 + w * 2;          // NE % 16 == 0
    int s0 = src[eg], d0 = dst[eg];
    int s1 = src[eg + 1], d1 = dst[eg + 1];
    float4 ce0 = ((const float4*)(g_eij + (size_t)eg * DD))[lane];
    float4 ce1 = ((const float4*)(g_eij + (size_t)(eg + 1) * DD))[lane];
    float4 dv0 = ((const float4*)(g_Dh + (size_t)s0 * DD))[lane];
    float4 dv1 = ((const float4*)(g_Dh + (size_t)s1 * DD))[lane];
    float4 ev0 = ((const float4*)(g_Eh + (size_t)d0 * DD))[lane];
    float4 ev1 = ((const float4*)(g_Eh + (size_t)d1 * DD))[lane];
    int c = lane * 4;
    float4 o0, o1;
    o0.x = fmaxf(0.f, (ce0.x + dv0.x + ev0.x - sM[c+0]) * sS[c+0] + sB[c+0]);
    o0.y = fmaxf(0.f, (ce0.y + dv0.y + ev0.y - sM[c+1]) * sS[c+1] + sB[c+1]);
    o0.z = fmaxf(0.f, (ce0.z + dv0.z + ev0.z - sM[c+2]) * sS[c+2] + sB[c+2]);
    o0.w = fmaxf(0.f, (ce0.w + dv0.w + ev0.w - sM[c+3]) * sS[c+3] + sB[c+3]);
    o1.x = fmaxf(0.f, (ce1.x + dv1.x + ev1.x - sM[c+0]) * sS[c+0] + sB[c+0]);
    o1.y = fmaxf(0.f, (ce1.y + dv1.y + ev1.y - sM[c+1]) * sS[c+1] + sB[c+1]);
    o1.z = fmaxf(0.f, (ce1.z + dv1.z + ev1.z - sM[c+2]) * sS[c+2] + sB[c+2]);
    o1.w = fmaxf(0.f, (ce1.w + dv1.w + ev1.w - sM[c+3]) * sS[c+3] + sB[c+3]);
    ((float4*)(out + (size_t)eg * DD))[lane] = o0;
    ((float4*)(out + (size_t)(eg + 1) * DD))[lane] = o1;
}

// ---------------- launch ------------------------------------------------------
extern "C" void kernel_launch(void* const* d_in, const int* in_sizes, int n_in,
                              void* d_out, int out_size) {
    const float* h   = (const float*)d_in[0];
    const float* e   = (const float*)d_in[1];
    const int*   src = (const int*)  d_in[2];
    const int*   dst = (const int*)  d_in[3];
    const float* WA  = (const float*)d_in[4];  const float* bA = (const float*)d_in[5];
    const float* WB  = (const float*)d_in[6];  const float* bB = (const float*)d_in[7];
    const float* WC  = (const float*)d_in[8];  const float* bC = (const float*)d_in[9];
    const float* WD  = (const float*)d_in[10]; const float* bD = (const float*)d_in[11];
    const float* WE  = (const float*)d_in[12]; const float* bE = (const float*)d_in[13];
    const float* gamma_h = (const float*)d_in[14]; const float* beta_h = (const float*)d_in[15];
    const float* gamma_e = (const float*)d_in[16]; const float* beta_e = (const float*)d_in[17];
    float* out = (float*)d_out;

    cudaFuncSetAttribute(k_node_hmma, cudaFuncAttributeMaxDynamicSharedMemorySize, SM_NODE_TOTAL);
    cudaFuncSetAttribute(k_edge_hmma, cudaFuncAttributeMaxDynamicSharedMemorySize, SM_EDGE_TOTAL);

    k_init<<<(NN + 255) / 256, 256>>>();
    k_deg<<<(NE + 255) / 256, 256>>>(dst);
    k_prep_w<<<dim3(64, 5), 256>>>(WA, WB, WC, WD, WE);
    k_scan1<<<49, 1024>>>();
    k_scan2<<<1, 1>>>();
    k_scan3<<<(NN + 255) / 256, 256>>>();
    k_scatter<<<(NE + 255) / 256, 256>>>(src, dst);
    k_node_hmma<<<NT_NODE, 512, SM_NODE_TOTAL>>>(h, bA, bB, bD, bE);
    k_edge_hmma<<<EGRID, 512, SM_EDGE_TOTAL>>>(e, bC);
    k_gather<<<NN, 128>>>();
    k_red<<<1, 256>>>();
    k_hout<<<(NN * 32 + 255) / 256, 256>>>(gamma_h, beta_h, out);
    k_eout<<<NE / 16, 256>>>(src, dst, gamma_e, beta_e, out + (size_t)NN * DD);
}